// round 1
// baseline (speedup 1.0000x reference)
#include <cuda_runtime.h>
#include <math.h>

#define NB 4
#define NT 2048
#define NDM 1024
#define NH 16
#define NDK 64

// Scratch for projected Q/K/V: [B,H,T,64] each = 33.55 MB each.
__device__ float g_q[NB*NH*NT*NDK];
__device__ float g_k[NB*NH*NT*NDK];
__device__ float g_v[NB*NH*NT*NDK];

// ---------------------------------------------------------------------------
// Projection GEMM: out[b,h,t,n] = sum_d x[b,t,d] * W[h,d,n]
// Tile: BM=128 (rows of x), BN=64 (one full head), BK=16. 256 threads,
// each thread computes an 8x4 microtile. blockIdx.z selects Wq/Wk/Wv.
// ---------------------------------------------------------------------------
__global__ __launch_bounds__(256) void proj_kernel(
    const float* __restrict__ x,
    const float* __restrict__ Wq,
    const float* __restrict__ Wk,
    const float* __restrict__ Wv)
{
    __shared__ float As[16 * 132];   // A transposed: As[k][m], stride 132
    __shared__ float Bs[16 * 68];    // Bs[k][n], stride 68

    const int h  = blockIdx.y;
    const int m0 = blockIdx.x * 128;

    const float* W;
    float* outp;
    if (blockIdx.z == 0)      { W = Wq; outp = g_q; }
    else if (blockIdx.z == 1) { W = Wk; outp = g_k; }
    else                      { W = Wv; outp = g_v; }
    W += (size_t)h * NDM * NDK;

    const int tid = threadIdx.x;
    const int tx  = tid & 15;        // column group (4 cols)
    const int ty  = tid >> 4;        // row group (8 rows)

    float acc[8][4];
    #pragma unroll
    for (int i = 0; i < 8; i++)
        #pragma unroll
        for (int j = 0; j < 4; j++) acc[i][j] = 0.0f;

    const int arow  = tid >> 1;          // 0..127
    const int ahalf = (tid & 1) * 8;     // which 8 of the 16 k's
    const int bkk   = tid >> 4;          // 0..15
    const int bn    = (tid & 15) * 4;    // 0..60

    for (int k0 = 0; k0 < NDM; k0 += 16) {
        // global loads first (overlap with previous compute)
        float4 a0 = *(const float4*)&x[(size_t)(m0 + arow) * NDM + k0 + ahalf];
        float4 a1 = *(const float4*)&x[(size_t)(m0 + arow) * NDM + k0 + ahalf + 4];
        float4 b0 = *(const float4*)&W[(size_t)(k0 + bkk) * NDK + bn];

        __syncthreads();   // previous iteration's reads done
        As[(ahalf + 0) * 132 + arow] = a0.x;
        As[(ahalf + 1) * 132 + arow] = a0.y;
        As[(ahalf + 2) * 132 + arow] = a0.z;
        As[(ahalf + 3) * 132 + arow] = a0.w;
        As[(ahalf + 4) * 132 + arow] = a1.x;
        As[(ahalf + 5) * 132 + arow] = a1.y;
        As[(ahalf + 6) * 132 + arow] = a1.z;
        As[(ahalf + 7) * 132 + arow] = a1.w;
        *(float4*)&Bs[bkk * 68 + bn] = b0;
        __syncthreads();

        #pragma unroll
        for (int kk = 0; kk < 16; kk++) {
            float a[8];
            *(float4*)&a[0] = *(const float4*)&As[kk * 132 + ty * 8];
            *(float4*)&a[4] = *(const float4*)&As[kk * 132 + ty * 8 + 4];
            float4 bv = *(const float4*)&Bs[kk * 68 + tx * 4];
            float bb[4] = {bv.x, bv.y, bv.z, bv.w};
            #pragma unroll
            for (int i = 0; i < 8; i++)
                #pragma unroll
                for (int j = 0; j < 4; j++)
                    acc[i][j] = fmaf(a[i], bb[j], acc[i][j]);
        }
    }

    // write out: out[((b*H+h)*T + t)*64 + n]
    const int b     = m0 >> 11;       // m0 / 2048
    const int tbase = m0 & 2047;
    #pragma unroll
    for (int i = 0; i < 8; i++) {
        int t = tbase + ty * 8 + i;
        size_t oidx = (((size_t)(b * NH + h)) * NT + t) * NDK + tx * 4;
        float4 r = make_float4(acc[i][0], acc[i][1], acc[i][2], acc[i][3]);
        *(float4*)&outp[oidx] = r;
    }
}

// ---------------------------------------------------------------------------
// Flash attention: one block per (q-tile of 64 rows, b*h). Causal skip.
// 256 threads, 4x4 S fragment per thread (ty: 16 row groups, tx: 16 col groups).
// Smem: Qs[64][68] + KtP[64][68] (K^T, reused for P) + Vs[64][68] = 52224 B.
// ---------------------------------------------------------------------------
__global__ __launch_bounds__(256) void attn_kernel(float* __restrict__ out)
{
    extern __shared__ float sm[];
    float* Qs  = sm;                 // Qs[r][d], stride 68
    float* KtP = sm + 64 * 68;       // Kt[d][s] then P[r][s], stride 68
    float* Vs  = sm + 2 * 64 * 68;   // Vs[s][v], stride 68

    const int qt = blockIdx.x;       // 0..31
    const int bh = blockIdx.y;       // 0..63
    const int b  = bh >> 4;
    const int h  = bh & 15;

    const float* qb = g_q + (size_t)bh * NT * NDK;
    const float* kb = g_k + (size_t)bh * NT * NDK;
    const float* vb = g_v + (size_t)bh * NT * NDK;

    const int q0  = qt * 64;
    const int tid = threadIdx.x;
    const int tx  = tid & 15;
    const int ty  = tid >> 4;

    // Load Q tile (natural layout)
    for (int i = tid; i < 1024; i += 256) {
        int r = i >> 4, c = (i & 15) * 4;
        float4 vq = *(const float4*)&qb[(size_t)(q0 + r) * NDK + c];
        *(float4*)&Qs[r * 68 + c] = vq;
    }

    float m_i[4], l_i[4], o[4][4];
    #pragma unroll
    for (int i = 0; i < 4; i++) {
        m_i[i] = -INFINITY;
        l_i[i] = 0.0f;
        #pragma unroll
        for (int j = 0; j < 4; j++) o[i][j] = 0.0f;
    }
    __syncthreads();

    for (int kt = 0; kt <= qt; kt++) {
        const int s0 = kt * 64;

        // Load K transposed: Kt[d][s]
        for (int e = tid; e < 4096; e += 256) {
            int s = e >> 6, d = e & 63;
            KtP[d * 68 + s] = kb[(size_t)(s0 + s) * NDK + d];
        }
        // Load V natural: Vs[s][v]
        for (int i = tid; i < 1024; i += 256) {
            int r = i >> 4, c = (i & 15) * 4;
            *(float4*)&Vs[r * 68 + c] = *(const float4*)&vb[(size_t)(s0 + r) * NDK + c];
        }
        __syncthreads();

        // --- GEMM1: S = Q * K^T  (4x4 fragment) ---
        float sf[4][4];
        #pragma unroll
        for (int i = 0; i < 4; i++)
            #pragma unroll
            for (int j = 0; j < 4; j++) sf[i][j] = 0.0f;

        #pragma unroll
        for (int d4 = 0; d4 < 64; d4 += 4) {
            float areg[4][4];
            #pragma unroll
            for (int i = 0; i < 4; i++)
                *(float4*)areg[i] = *(const float4*)&Qs[(ty * 4 + i) * 68 + d4];
            #pragma unroll
            for (int dd = 0; dd < 4; dd++) {
                float4 bq = *(const float4*)&KtP[(d4 + dd) * 68 + tx * 4];
                float bb[4] = {bq.x, bq.y, bq.z, bq.w};
                #pragma unroll
                for (int i = 0; i < 4; i++)
                    #pragma unroll
                    for (int j = 0; j < 4; j++)
                        sf[i][j] = fmaf(areg[i][dd], bb[j], sf[i][j]);
            }
        }

        // scale + causal mask (only the diagonal tile needs masking)
        #pragma unroll
        for (int i = 0; i < 4; i++)
            #pragma unroll
            for (int j = 0; j < 4; j++) sf[i][j] *= 0.125f;  // DK^-0.5

        if (kt == qt) {
            #pragma unroll
            for (int i = 0; i < 4; i++) {
                int qr = q0 + ty * 4 + i;
                #pragma unroll
                for (int j = 0; j < 4; j++)
                    if (s0 + tx * 4 + j > qr) sf[i][j] = -INFINITY;
            }
        }

        // --- online softmax (row reduction across the 16 tx lanes) ---
        #pragma unroll
        for (int i = 0; i < 4; i++) {
            float rmax = fmaxf(fmaxf(sf[i][0], sf[i][1]), fmaxf(sf[i][2], sf[i][3]));
            #pragma unroll
            for (int off = 1; off < 16; off <<= 1)
                rmax = fmaxf(rmax, __shfl_xor_sync(0xffffffffu, rmax, off));
            float mnew  = fmaxf(m_i[i], rmax);
            float alpha = __expf(m_i[i] - mnew);
            float rsum  = 0.0f;
            #pragma unroll
            for (int j = 0; j < 4; j++) {
                sf[i][j] = __expf(sf[i][j] - mnew);
                rsum += sf[i][j];
            }
            #pragma unroll
            for (int off = 1; off < 16; off <<= 1)
                rsum += __shfl_xor_sync(0xffffffffu, rsum, off);
            l_i[i] = l_i[i] * alpha + rsum;
            m_i[i] = mnew;
            #pragma unroll
            for (int j = 0; j < 4; j++) o[i][j] *= alpha;
        }

        __syncthreads();   // everyone is done reading Kt before P overwrites it
        #pragma unroll
        for (int i = 0; i < 4; i++) {
            float4 pv = make_float4(sf[i][0], sf[i][1], sf[i][2], sf[i][3]);
            *(float4*)&KtP[(ty * 4 + i) * 68 + tx * 4] = pv;
        }
        __syncthreads();

        // --- GEMM2: O += P * V ---
        #pragma unroll
        for (int s4 = 0; s4 < 64; s4 += 4) {
            float preg[4][4];
            #pragma unroll
            for (int i = 0; i < 4; i++)
                *(float4*)preg[i] = *(const float4*)&KtP[(ty * 4 + i) * 68 + s4];
            #pragma unroll
            for (int ss = 0; ss < 4; ss++) {
                float4 vv = *(const float4*)&Vs[(s4 + ss) * 68 + tx * 4];
                float bb[4] = {vv.x, vv.y, vv.z, vv.w};
                #pragma unroll
                for (int i = 0; i < 4; i++)
                    #pragma unroll
                    for (int j = 0; j < 4; j++)
                        o[i][j] = fmaf(preg[i][ss], bb[j], o[i][j]);
            }
        }
        __syncthreads();   // before next iteration's loads overwrite KtP/Vs
    }

    // finalize: divide by l, write out[b, t, h*64 + v]
    #pragma unroll
    for (int i = 0; i < 4; i++) {
        float inv = 1.0f / l_i[i];
        int t = q0 + ty * 4 + i;
        size_t oidx = (((size_t)b * NT) + t) * (NH * NDK) + h * NDK + tx * 4;
        float4 r = make_float4(o[i][0] * inv, o[i][1] * inv,
                               o[i][2] * inv, o[i][3] * inv);
        *(float4*)&out[oidx] = r;
    }
}

// ---------------------------------------------------------------------------
extern "C" void kernel_launch(void* const* d_in, const int* in_sizes, int n_in,
                              void* d_out, int out_size)
{
    (void)in_sizes; (void)n_in; (void)out_size;
    const float* x  = (const float*)d_in[0];
    const float* Wq = (const float*)d_in[1];
    const float* Wk = (const float*)d_in[2];
    const float* Wv = (const float*)d_in[3];
    float* out = (float*)d_out;

    const int attn_smem = 3 * 64 * 68 * (int)sizeof(float);  // 52224 B
    cudaFuncSetAttribute(attn_kernel,
                         cudaFuncAttributeMaxDynamicSharedMemorySize, attn_smem);

    dim3 pg(NB * NT / 128, NH, 3);     // 64 x 16 x 3
    proj_kernel<<<pg, 256>>>(x, Wq, Wk, Wv);

    dim3 ag(NT / 64, NB * NH);         // 32 x 64
    attn_kernel<<<ag, 256, attn_smem>>>(out);
}

// round 3
// speedup vs baseline: 1.4167x; 1.4167x over previous
#include <cuda_runtime.h>
#include <math.h>
#include <stdint.h>

#define NB 4
#define NT 2048
#define NDM 1024
#define NH 16
#define NDK 64

// Scratch for projected Q/K/V: [B,H,T,64] each.
__device__ float g_q[NB*NH*NT*NDK];
__device__ float g_k[NB*NH*NT*NDK];
__device__ float g_v[NB*NH*NT*NDK];

__device__ __forceinline__ float to_tf32(float f) {
    float r; asm("cvt.rna.tf32.f32 %0, %1;" : "=f"(r) : "f"(f)); return r;
}
__device__ __forceinline__ void mma_tf32(float* c, const uint32_t* a, const uint32_t* b) {
    asm volatile("mma.sync.aligned.m16n8k8.row.col.f32.tf32.tf32.f32 "
                 "{%0,%1,%2,%3}, {%4,%5,%6,%7}, {%8,%9}, {%0,%1,%2,%3};"
                 : "+f"(c[0]), "+f"(c[1]), "+f"(c[2]), "+f"(c[3])
                 : "r"(a[0]), "r"(a[1]), "r"(a[2]), "r"(a[3]),
                   "r"(b[0]), "r"(b[1]));
}

// ---------------------------------------------------------------------------
// Projection GEMM on mma.sync tf32.
// CTA: M=128 (x rows) x N=64 (one head) x K=1024 staged by 32, double buffer.
// 8 warps, each computes a 32x32 tile (2 x 4 m16n8k8 fragments per k-step).
// As[128][36] (pad), Bs[32][72] (pad) per stage; both fragment LDS patterns
// are bank-conflict-free (4qr+qc and 8qc+qr).
// ---------------------------------------------------------------------------
#define AS_STRIDE 36
#define BS_STRIDE 72
#define STAGE_FLOATS (128 * AS_STRIDE + 32 * BS_STRIDE)   // 6912
#define BS_OFF (128 * AS_STRIDE)                          // 4608
#define PROJ_SMEM (2 * STAGE_FLOATS * 4)                  // 55296 B

__global__ __launch_bounds__(256, 2) void proj_mma(
    const float* __restrict__ x,
    const float* __restrict__ Wq,
    const float* __restrict__ Wk,
    const float* __restrict__ Wv)
{
    extern __shared__ float sm[];

    const int m0 = blockIdx.x * 128;
    const int h  = blockIdx.y;
    const int z  = blockIdx.z;
    const float* W = ((z == 0) ? Wq : (z == 1) ? Wk : Wv) + (size_t)h * NDM * NDK;
    float* outp    = ((z == 0) ? g_q : (z == 1) ? g_k : g_v);

    const int tid  = threadIdx.x;
    const int wid  = tid >> 5;
    const int lane = tid & 31;
    const int qr   = lane >> 2;        // 0..7
    const int qc   = lane & 3;         // 0..3
    const int wr   = wid >> 1;         // 0..3 : m offset wr*32
    const int wc   = wid & 1;          // 0..1 : n offset wc*32

    // Per-thread load indices (stage-invariant)
    // A: 1024 float4s, thread does 4: q = tid + j*256 -> row=q>>3, col4=(q&7)*4
    int arow[4], acol[4];
    #pragma unroll
    for (int j = 0; j < 4; j++) {
        int q = tid + j * 256;
        arow[j] = q >> 3; acol[j] = (q & 7) * 4;
    }
    // B: 512 float4s, thread does 2: q = tid + j*256 -> row=q>>4, col4=(q&15)*4
    int brow[2], bcol[2];
    #pragma unroll
    for (int j = 0; j < 2; j++) {
        int q = tid + j * 256;
        brow[j] = q >> 4; bcol[j] = (q & 15) * 4;
    }

    float acc[2][4][4];
    #pragma unroll
    for (int mi = 0; mi < 2; mi++)
        #pragma unroll
        for (int ni = 0; ni < 4; ni++)
            #pragma unroll
            for (int v = 0; v < 4; v++) acc[mi][ni][v] = 0.0f;

    // ---- prologue: load stage 0 ----
    {
        float* As = sm;
        float* Bs = sm + BS_OFF;
        #pragma unroll
        for (int j = 0; j < 4; j++) {
            float4 v = *(const float4*)&x[(size_t)(m0 + arow[j]) * NDM + acol[j]];
            v.x = to_tf32(v.x); v.y = to_tf32(v.y);
            v.z = to_tf32(v.z); v.w = to_tf32(v.w);
            *(float4*)&As[arow[j] * AS_STRIDE + acol[j]] = v;
        }
        #pragma unroll
        for (int j = 0; j < 2; j++) {
            float4 v = *(const float4*)&W[(size_t)brow[j] * NDK + bcol[j]];
            v.x = to_tf32(v.x); v.y = to_tf32(v.y);
            v.z = to_tf32(v.z); v.w = to_tf32(v.w);
            *(float4*)&Bs[brow[j] * BS_STRIDE + bcol[j]] = v;
        }
    }
    __syncthreads();

    // ---- main loop over K stages ----
    for (int s = 0; s < 32; s++) {
        // prefetch next stage into registers
        float4 pa[4], pb[2];
        if (s + 1 < 32) {
            const int k1 = (s + 1) * 32;
            #pragma unroll
            for (int j = 0; j < 4; j++)
                pa[j] = *(const float4*)&x[(size_t)(m0 + arow[j]) * NDM + k1 + acol[j]];
            #pragma unroll
            for (int j = 0; j < 2; j++)
                pb[j] = *(const float4*)&W[(size_t)(k1 + brow[j]) * NDK + bcol[j]];
        }

        // compute from current buffer
        const float* As = sm + (s & 1) * STAGE_FLOATS;
        const float* Bs = As + BS_OFF;
        #pragma unroll
        for (int ks = 0; ks < 4; ks++) {
            const int k = ks * 8;
            uint32_t af[2][4], bf[4][2];
            #pragma unroll
            for (int mi = 0; mi < 2; mi++) {
                const int rb = wr * 32 + mi * 16 + qr;
                af[mi][0] = __float_as_uint(As[(rb    ) * AS_STRIDE + k + qc]);
                af[mi][1] = __float_as_uint(As[(rb + 8) * AS_STRIDE + k + qc]);
                af[mi][2] = __float_as_uint(As[(rb    ) * AS_STRIDE + k + 4 + qc]);
                af[mi][3] = __float_as_uint(As[(rb + 8) * AS_STRIDE + k + 4 + qc]);
            }
            #pragma unroll
            for (int ni = 0; ni < 4; ni++) {
                const int cb = wc * 32 + ni * 8 + qr;
                bf[ni][0] = __float_as_uint(Bs[(k + qc    ) * BS_STRIDE + cb]);
                bf[ni][1] = __float_as_uint(Bs[(k + 4 + qc) * BS_STRIDE + cb]);
            }
            #pragma unroll
            for (int mi = 0; mi < 2; mi++)
                #pragma unroll
                for (int ni = 0; ni < 4; ni++)
                    mma_tf32(acc[mi][ni], af[mi], bf[ni]);
        }

        // store prefetched stage
        if (s + 1 < 32) {
            float* Asn = sm + ((s + 1) & 1) * STAGE_FLOATS;
            float* Bsn = Asn + BS_OFF;
            #pragma unroll
            for (int j = 0; j < 4; j++) {
                float4 v = pa[j];
                v.x = to_tf32(v.x); v.y = to_tf32(v.y);
                v.z = to_tf32(v.z); v.w = to_tf32(v.w);
                *(float4*)&Asn[arow[j] * AS_STRIDE + acol[j]] = v;
            }
            #pragma unroll
            for (int j = 0; j < 2; j++) {
                float4 v = pb[j];
                v.x = to_tf32(v.x); v.y = to_tf32(v.y);
                v.z = to_tf32(v.z); v.w = to_tf32(v.w);
                *(float4*)&Bsn[brow[j] * BS_STRIDE + bcol[j]] = v;
            }
        }
        __syncthreads();
    }

    // ---- epilogue: write out[((b*H+h)*T + t)*64 + n] ----
    const int b     = m0 >> 11;
    const int tbase = m0 & 2047;
    #pragma unroll
    for (int mi = 0; mi < 2; mi++) {
        #pragma unroll
        for (int ni = 0; ni < 4; ni++) {
            const int n = wc * 32 + ni * 8 + 2 * qc;
            int t0 = tbase + wr * 32 + mi * 16 + qr;
            size_t base0 = (((size_t)(b * NH + h)) * NT + t0) * NDK + n;
            size_t base1 = base0 + 8 * NDK;   // qr+8 row
            *(float2*)&outp[base0] = make_float2(acc[mi][ni][0], acc[mi][ni][1]);
            *(float2*)&outp[base1] = make_float2(acc[mi][ni][2], acc[mi][ni][3]);
        }
    }
}

// ---------------------------------------------------------------------------
// Flash attention (unchanged, known-good): fp32 SIMT, causal skip.
// ---------------------------------------------------------------------------
__global__ __launch_bounds__(256) void attn_kernel(float* __restrict__ out)
{
    extern __shared__ float smf[];
    float* Qs  = smf;
    float* KtP = smf + 64 * 68;
    float* Vs  = smf + 2 * 64 * 68;

    const int qt = blockIdx.x;
    const int bh = blockIdx.y;
    const int b  = bh >> 4;
    const int h  = bh & 15;

    const float* qb = g_q + (size_t)bh * NT * NDK;
    const float* kb = g_k + (size_t)bh * NT * NDK;
    const float* vb = g_v + (size_t)bh * NT * NDK;

    const int q0  = qt * 64;
    const int tid = threadIdx.x;
    const int tx  = tid & 15;
    const int ty  = tid >> 4;

    for (int i = tid; i < 1024; i += 256) {
        int r = i >> 4, c = (i & 15) * 4;
        float4 vq = *(const float4*)&qb[(size_t)(q0 + r) * NDK + c];
        *(float4*)&Qs[r * 68 + c] = vq;
    }

    float m_i[4], l_i[4], o[4][4];
    #pragma unroll
    for (int i = 0; i < 4; i++) {
        m_i[i] = -INFINITY; l_i[i] = 0.0f;
        #pragma unroll
        for (int j = 0; j < 4; j++) o[i][j] = 0.0f;
    }
    __syncthreads();

    for (int kt = 0; kt <= qt; kt++) {
        const int s0 = kt * 64;
        for (int e = tid; e < 4096; e += 256) {
            int s = e >> 6, d = e & 63;
            KtP[d * 68 + s] = kb[(size_t)(s0 + s) * NDK + d];
        }
        for (int i = tid; i < 1024; i += 256) {
            int r = i >> 4, c = (i & 15) * 4;
            *(float4*)&Vs[r * 68 + c] = *(const float4*)&vb[(size_t)(s0 + r) * NDK + c];
        }
        __syncthreads();

        float sf[4][4];
        #pragma unroll
        for (int i = 0; i < 4; i++)
            #pragma unroll
            for (int j = 0; j < 4; j++) sf[i][j] = 0.0f;

        #pragma unroll
        for (int d4 = 0; d4 < 64; d4 += 4) {
            float areg[4][4];
            #pragma unroll
            for (int i = 0; i < 4; i++)
                *(float4*)areg[i] = *(const float4*)&Qs[(ty * 4 + i) * 68 + d4];
            #pragma unroll
            for (int dd = 0; dd < 4; dd++) {
                float4 bq = *(const float4*)&KtP[(d4 + dd) * 68 + tx * 4];
                float bb[4] = {bq.x, bq.y, bq.z, bq.w};
                #pragma unroll
                for (int i = 0; i < 4; i++)
                    #pragma unroll
                    for (int j = 0; j < 4; j++)
                        sf[i][j] = fmaf(areg[i][dd], bb[j], sf[i][j]);
            }
        }

        #pragma unroll
        for (int i = 0; i < 4; i++)
            #pragma unroll
            for (int j = 0; j < 4; j++) sf[i][j] *= 0.125f;

        if (kt == qt) {
            #pragma unroll
            for (int i = 0; i < 4; i++) {
                int qr2 = q0 + ty * 4 + i;
                #pragma unroll
                for (int j = 0; j < 4; j++)
                    if (s0 + tx * 4 + j > qr2) sf[i][j] = -INFINITY;
            }
        }

        #pragma unroll
        for (int i = 0; i < 4; i++) {
            float rmax = fmaxf(fmaxf(sf[i][0], sf[i][1]), fmaxf(sf[i][2], sf[i][3]));
            #pragma unroll
            for (int off = 1; off < 16; off <<= 1)
                rmax = fmaxf(rmax, __shfl_xor_sync(0xffffffffu, rmax, off));
            float mnew  = fmaxf(m_i[i], rmax);
            float alpha = __expf(m_i[i] - mnew);
            float rsum  = 0.0f;
            #pragma unroll
            for (int j = 0; j < 4; j++) {
                sf[i][j] = __expf(sf[i][j] - mnew);
                rsum += sf[i][j];
            }
            #pragma unroll
            for (int off = 1; off < 16; off <<= 1)
                rsum += __shfl_xor_sync(0xffffffffu, rsum, off);
            l_i[i] = l_i[i] * alpha + rsum;
            m_i[i] = mnew;
            #pragma unroll
            for (int j = 0; j < 4; j++) o[i][j] *= alpha;
        }

        __syncthreads();
        #pragma unroll
        for (int i = 0; i < 4; i++) {
            float4 pv = make_float4(sf[i][0], sf[i][1], sf[i][2], sf[i][3]);
            *(float4*)&KtP[(ty * 4 + i) * 68 + tx * 4] = pv;
        }
        __syncthreads();

        #pragma unroll
        for (int s4 = 0; s4 < 64; s4 += 4) {
            float preg[4][4];
            #pragma unroll
            for (int i = 0; i < 4; i++)
                *(float4*)preg[i] = *(const float4*)&KtP[(ty * 4 + i) * 68 + s4];
            #pragma unroll
            for (int ss = 0; ss < 4; ss++) {
                float4 vv = *(const float4*)&Vs[(s4 + ss) * 68 + tx * 4];
                float bb[4] = {vv.x, vv.y, vv.z, vv.w};
                #pragma unroll
                for (int i = 0; i < 4; i++)
                    #pragma unroll
                    for (int j = 0; j < 4; j++)
                        o[i][j] = fmaf(preg[i][ss], bb[j], o[i][j]);
            }
        }
        __syncthreads();
    }

    #pragma unroll
    for (int i = 0; i < 4; i++) {
        float inv = 1.0f / l_i[i];
        int t = q0 + ty * 4 + i;
        size_t oidx = (((size_t)b * NT) + t) * (NH * NDK) + h * NDK + tx * 4;
        float4 r = make_float4(o[i][0] * inv, o[i][1] * inv,
                               o[i][2] * inv, o[i][3] * inv);
        *(float4*)&out[oidx] = r;
    }
}

// ---------------------------------------------------------------------------
extern "C" void kernel_launch(void* const* d_in, const int* in_sizes, int n_in,
                              void* d_out, int out_size)
{
    (void)in_sizes; (void)n_in; (void)out_size;
    const float* x  = (const float*)d_in[0];
    const float* Wq = (const float*)d_in[1];
    const float* Wk = (const float*)d_in[2];
    const float* Wv = (const float*)d_in[3];
    float* out = (float*)d_out;

    cudaFuncSetAttribute(proj_mma,
                         cudaFuncAttributeMaxDynamicSharedMemorySize, PROJ_SMEM);
    const int attn_smem = 3 * 64 * 68 * (int)sizeof(float);
    cudaFuncSetAttribute(attn_kernel,
                         cudaFuncAttributeMaxDynamicSharedMemorySize, attn_smem);

    proj_mma<<<dim3(NB * NT / 128, NH, 3), 256, PROJ_SMEM>>>(x, Wq, Wk, Wv);

    dim3 ag(NT / 64, NB * NH);
    attn_kernel<<<ag, 256, attn_smem>>>(out);
}

// round 4
// speedup vs baseline: 2.9364x; 2.0727x over previous
#include <cuda_runtime.h>
#include <math.h>
#include <stdint.h>

#define NB 4
#define NT 2048
#define NDM 1024
#define NH 16
#define NDK 64

// Scratch for projected Q/K/V: [B,H,T,64] each (tf32-rounded values).
__device__ float g_q[NB*NH*NT*NDK];
__device__ float g_k[NB*NH*NT*NDK];
__device__ float g_v[NB*NH*NT*NDK];

__device__ __forceinline__ float to_tf32(float f) {
    float r; asm("cvt.rna.tf32.f32 %0, %1;" : "=f"(r) : "f"(f)); return r;
}
__device__ __forceinline__ void mma_tf32(float* c, const uint32_t* a, const uint32_t* b) {
    asm volatile("mma.sync.aligned.m16n8k8.row.col.f32.tf32.tf32.f32 "
                 "{%0,%1,%2,%3}, {%4,%5,%6,%7}, {%8,%9}, {%0,%1,%2,%3};"
                 : "+f"(c[0]), "+f"(c[1]), "+f"(c[2]), "+f"(c[3])
                 : "r"(a[0]), "r"(a[1]), "r"(a[2]), "r"(a[3]),
                   "r"(b[0]), "r"(b[1]));
}
__device__ __forceinline__ uint32_t smem_u32(const void* p) {
    uint32_t a;
    asm("{ .reg .u64 t; cvta.to.shared.u64 t, %1; cvt.u32.u64 %0, t; }"
        : "=r"(a) : "l"(p));
    return a;
}
#define CP_ASYNC16(dst, src) \
    asm volatile("cp.async.cg.shared.global [%0], [%1], 16;" \
                 :: "r"(dst), "l"(src) : "memory")
#define CP_COMMIT  asm volatile("cp.async.commit_group;" ::: "memory")
#define CP_WAIT(n) asm volatile("cp.async.wait_group %0;" :: "n"(n) : "memory")

// ---------------------------------------------------------------------------
// Projection GEMM on mma.sync tf32 (round-3, + tf32-rounded outputs).
// ---------------------------------------------------------------------------
#define AS_STRIDE 36
#define BS_STRIDE 72
#define STAGE_FLOATS (128 * AS_STRIDE + 32 * BS_STRIDE)
#define BS_OFF (128 * AS_STRIDE)
#define PROJ_SMEM (2 * STAGE_FLOATS * 4)

__global__ __launch_bounds__(256, 2) void proj_mma(
    const float* __restrict__ x,
    const float* __restrict__ Wq,
    const float* __restrict__ Wk,
    const float* __restrict__ Wv)
{
    extern __shared__ float sm[];

    const int m0 = blockIdx.x * 128;
    const int h  = blockIdx.y;
    const int z  = blockIdx.z;
    const float* W = ((z == 0) ? Wq : (z == 1) ? Wk : Wv) + (size_t)h * NDM * NDK;
    float* outp    = ((z == 0) ? g_q : (z == 1) ? g_k : g_v);

    const int tid  = threadIdx.x;
    const int wid  = tid >> 5;
    const int lane = tid & 31;
    const int qr   = lane >> 2;
    const int qc   = lane & 3;
    const int wr   = wid >> 1;
    const int wc   = wid & 1;

    int arow[4], acol[4];
    #pragma unroll
    for (int j = 0; j < 4; j++) {
        int q = tid + j * 256;
        arow[j] = q >> 3; acol[j] = (q & 7) * 4;
    }
    int brow[2], bcol[2];
    #pragma unroll
    for (int j = 0; j < 2; j++) {
        int q = tid + j * 256;
        brow[j] = q >> 4; bcol[j] = (q & 15) * 4;
    }

    float acc[2][4][4];
    #pragma unroll
    for (int mi = 0; mi < 2; mi++)
        #pragma unroll
        for (int ni = 0; ni < 4; ni++)
            #pragma unroll
            for (int v = 0; v < 4; v++) acc[mi][ni][v] = 0.0f;

    {
        float* As = sm;
        float* Bs = sm + BS_OFF;
        #pragma unroll
        for (int j = 0; j < 4; j++) {
            float4 v = *(const float4*)&x[(size_t)(m0 + arow[j]) * NDM + acol[j]];
            v.x = to_tf32(v.x); v.y = to_tf32(v.y);
            v.z = to_tf32(v.z); v.w = to_tf32(v.w);
            *(float4*)&As[arow[j] * AS_STRIDE + acol[j]] = v;
        }
        #pragma unroll
        for (int j = 0; j < 2; j++) {
            float4 v = *(const float4*)&W[(size_t)brow[j] * NDK + bcol[j]];
            v.x = to_tf32(v.x); v.y = to_tf32(v.y);
            v.z = to_tf32(v.z); v.w = to_tf32(v.w);
            *(float4*)&Bs[brow[j] * BS_STRIDE + bcol[j]] = v;
        }
    }
    __syncthreads();

    for (int s = 0; s < 32; s++) {
        float4 pa[4], pb[2];
        if (s + 1 < 32) {
            const int k1 = (s + 1) * 32;
            #pragma unroll
            for (int j = 0; j < 4; j++)
                pa[j] = *(const float4*)&x[(size_t)(m0 + arow[j]) * NDM + k1 + acol[j]];
            #pragma unroll
            for (int j = 0; j < 2; j++)
                pb[j] = *(const float4*)&W[(size_t)(k1 + brow[j]) * NDK + bcol[j]];
        }

        const float* As = sm + (s & 1) * STAGE_FLOATS;
        const float* Bs = As + BS_OFF;
        #pragma unroll
        for (int ks = 0; ks < 4; ks++) {
            const int k = ks * 8;
            uint32_t af[2][4], bf[4][2];
            #pragma unroll
            for (int mi = 0; mi < 2; mi++) {
                const int rb = wr * 32 + mi * 16 + qr;
                af[mi][0] = __float_as_uint(As[(rb    ) * AS_STRIDE + k + qc]);
                af[mi][1] = __float_as_uint(As[(rb + 8) * AS_STRIDE + k + qc]);
                af[mi][2] = __float_as_uint(As[(rb    ) * AS_STRIDE + k + 4 + qc]);
                af[mi][3] = __float_as_uint(As[(rb + 8) * AS_STRIDE + k + 4 + qc]);
            }
            #pragma unroll
            for (int ni = 0; ni < 4; ni++) {
                const int cb = wc * 32 + ni * 8 + qr;
                bf[ni][0] = __float_as_uint(Bs[(k + qc    ) * BS_STRIDE + cb]);
                bf[ni][1] = __float_as_uint(Bs[(k + 4 + qc) * BS_STRIDE + cb]);
            }
            #pragma unroll
            for (int mi = 0; mi < 2; mi++)
                #pragma unroll
                for (int ni = 0; ni < 4; ni++)
                    mma_tf32(acc[mi][ni], af[mi], bf[ni]);
        }

        if (s + 1 < 32) {
            float* Asn = sm + ((s + 1) & 1) * STAGE_FLOATS;
            float* Bsn = Asn + BS_OFF;
            #pragma unroll
            for (int j = 0; j < 4; j++) {
                float4 v = pa[j];
                v.x = to_tf32(v.x); v.y = to_tf32(v.y);
                v.z = to_tf32(v.z); v.w = to_tf32(v.w);
                *(float4*)&Asn[arow[j] * AS_STRIDE + acol[j]] = v;
            }
            #pragma unroll
            for (int j = 0; j < 2; j++) {
                float4 v = pb[j];
                v.x = to_tf32(v.x); v.y = to_tf32(v.y);
                v.z = to_tf32(v.z); v.w = to_tf32(v.w);
                *(float4*)&Bsn[brow[j] * BS_STRIDE + bcol[j]] = v;
            }
        }
        __syncthreads();
    }

    const int b     = m0 >> 11;
    const int tbase = m0 & 2047;
    #pragma unroll
    for (int mi = 0; mi < 2; mi++) {
        #pragma unroll
        for (int ni = 0; ni < 4; ni++) {
            const int n = wc * 32 + ni * 8 + 2 * qc;
            int t0 = tbase + wr * 32 + mi * 16 + qr;
            size_t base0 = (((size_t)(b * NH + h)) * NT + t0) * NDK + n;
            size_t base1 = base0 + 8 * NDK;
            // round outputs to tf32 so attention mma operands are exact tf32
            *(float2*)&outp[base0] = make_float2(to_tf32(acc[mi][ni][0]),
                                                 to_tf32(acc[mi][ni][1]));
            *(float2*)&outp[base1] = make_float2(to_tf32(acc[mi][ni][2]),
                                                 to_tf32(acc[mi][ni][3]));
        }
    }
}

// ---------------------------------------------------------------------------
// Flash attention on mma.sync tf32.
// CTA: 128-query tile x one (b,h). 8 warps; each warp owns a 16x64 S strip.
// Key tiles of 64, double-buffered K/V via cp.async. Q fragments in registers
// (scale 1/8 folded in). P round-trips through the warp-private Q smem strip.
// Smem floats: Qs/P 128x68 | K 2x 64x68 | V 2x 64x72  = 26624 (106496 B).
// ---------------------------------------------------------------------------
#define ATT_SMEM (26624 * 4)

__global__ __launch_bounds__(256, 2) void attn_mma(float* __restrict__ out)
{
    extern __shared__ float sm[];
    float* Qs = sm;   // 128 x 68 (Q staging, then per-warp P strips)

    const int qt = 15 - (int)blockIdx.x;    // big tiles first
    const int bh = blockIdx.y;
    const int b  = bh >> 4;
    const int h  = bh & 15;
    const int q0 = qt * 128;

    const float* qg = g_q + (size_t)bh * NT * NDK;
    const float* kg = g_k + (size_t)bh * NT * NDK;
    const float* vg = g_v + (size_t)bh * NT * NDK;

    const int tid  = threadIdx.x;
    const int wid  = tid >> 5;
    const int lane = tid & 31;
    const int qr   = lane >> 2;
    const int qc   = lane & 3;

    const uint32_t smb = smem_u32(sm);

    // ---- Q staging (group A) ----
    #pragma unroll
    for (int j = 0; j < 8; j++) {
        int q = tid + j * 256;
        int row = q >> 4, c4 = (q & 15) * 4;
        CP_ASYNC16(smb + (uint32_t)(row * 68 + c4) * 4,
                   qg + (size_t)(q0 + row) * NDK + c4);
    }
    CP_COMMIT;

    // ---- K/V tile 0 (group B) ----
    #pragma unroll
    for (int j = 0; j < 4; j++) {
        int q = tid + j * 256;
        int row = q >> 4, c4 = (q & 15) * 4;
        CP_ASYNC16(smb + (uint32_t)(8704 + row * 68 + c4) * 4,
                   kg + (size_t)row * NDK + c4);
        CP_ASYNC16(smb + (uint32_t)(17408 + row * 72 + c4) * 4,
                   vg + (size_t)row * NDK + c4);
    }
    CP_COMMIT;

    CP_WAIT(1);           // Q done (tile 0 may still be in flight)
    __syncthreads();

    // ---- Q fragments to registers (x 1/8 scale, exact in tf32) ----
    uint32_t qf[8][4];
    {
        const float* Qw = Qs + (wid * 16) * 68;
        #pragma unroll
        for (int ks = 0; ks < 8; ks++) {
            const int k = ks * 8;
            qf[ks][0] = __float_as_uint(Qw[(qr    ) * 68 + k + qc    ] * 0.125f);
            qf[ks][1] = __float_as_uint(Qw[(qr + 8) * 68 + k + qc    ] * 0.125f);
            qf[ks][2] = __float_as_uint(Qw[(qr    ) * 68 + k + 4 + qc] * 0.125f);
            qf[ks][3] = __float_as_uint(Qw[(qr + 8) * 68 + k + 4 + qc] * 0.125f);
        }
    }

    float o[8][4];
    #pragma unroll
    for (int ni = 0; ni < 8; ni++)
        #pragma unroll
        for (int v = 0; v < 4; v++) o[ni][v] = 0.0f;
    float m0 = -INFINITY, m1 = -INFINITY, l0 = 0.0f, l1 = 0.0f;

    const int ntiles = 2 * qt + 2;

    for (int kt = 0; kt < ntiles; kt++) {
        // prefetch next K/V tile
        if (kt + 1 < ntiles) {
            const int s1 = (kt + 1) * 64;
            const uint32_t kb = 8704  + ((kt + 1) & 1) * 4352;
            const uint32_t vb = 17408 + ((kt + 1) & 1) * 4608;
            #pragma unroll
            for (int j = 0; j < 4; j++) {
                int q = tid + j * 256;
                int row = q >> 4, c4 = (q & 15) * 4;
                CP_ASYNC16(smb + (kb + row * 68 + c4) * 4,
                           kg + (size_t)(s1 + row) * NDK + c4);
                CP_ASYNC16(smb + (vb + row * 72 + c4) * 4,
                           vg + (size_t)(s1 + row) * NDK + c4);
            }
            CP_COMMIT;
            CP_WAIT(1);
        } else {
            CP_WAIT(0);
        }
        __syncthreads();   // current tile visible to all warps

        const float* K_ = sm + 8704  + (kt & 1) * 4352;
        const float* V_ = sm + 17408 + (kt & 1) * 4608;
        const int s0 = kt * 64;

        // ---- S = (Q/8) K^T ----
        float sc[8][4];
        #pragma unroll
        for (int ni = 0; ni < 8; ni++)
            #pragma unroll
            for (int v = 0; v < 4; v++) sc[ni][v] = 0.0f;

        #pragma unroll
        for (int ni = 0; ni < 8; ni++) {
            const int cb = ni * 8 + qr;
            #pragma unroll
            for (int ks = 0; ks < 8; ks++) {
                const int k = ks * 8;
                uint32_t bf[2];
                bf[0] = __float_as_uint(K_[cb * 68 + k + qc    ]);
                bf[1] = __float_as_uint(K_[cb * 68 + k + 4 + qc]);
                mma_tf32(sc[ni], qf[ks], bf);
            }
        }

        // ---- causal mask (diagonal-overlap tiles only) ----
        if (kt >= 2 * qt) {
            const int r0g = q0 + wid * 16 + qr;
            const int r1g = r0g + 8;
            #pragma unroll
            for (int ni = 0; ni < 8; ni++) {
                const int c = s0 + ni * 8 + 2 * qc;
                if (c     > r0g) sc[ni][0] = -INFINITY;
                if (c + 1 > r0g) sc[ni][1] = -INFINITY;
                if (c     > r1g) sc[ni][2] = -INFINITY;
                if (c + 1 > r1g) sc[ni][3] = -INFINITY;
            }
        }

        // ---- online softmax (quad shfl row reductions) ----
        float rmax0 = sc[0][0], rmax1 = sc[0][2];
        #pragma unroll
        for (int ni = 0; ni < 8; ni++) {
            rmax0 = fmaxf(rmax0, fmaxf(sc[ni][0], sc[ni][1]));
            rmax1 = fmaxf(rmax1, fmaxf(sc[ni][2], sc[ni][3]));
        }
        rmax0 = fmaxf(rmax0, __shfl_xor_sync(0xffffffffu, rmax0, 1));
        rmax0 = fmaxf(rmax0, __shfl_xor_sync(0xffffffffu, rmax0, 2));
        rmax1 = fmaxf(rmax1, __shfl_xor_sync(0xffffffffu, rmax1, 1));
        rmax1 = fmaxf(rmax1, __shfl_xor_sync(0xffffffffu, rmax1, 2));

        const float mn0 = fmaxf(m0, rmax0);
        const float mn1 = fmaxf(m1, rmax1);
        const float a0  = __expf(m0 - mn0);
        const float a1  = __expf(m1 - mn1);

        float rs0 = 0.0f, rs1 = 0.0f;
        #pragma unroll
        for (int ni = 0; ni < 8; ni++) {
            sc[ni][0] = __expf(sc[ni][0] - mn0);
            sc[ni][1] = __expf(sc[ni][1] - mn0);
            sc[ni][2] = __expf(sc[ni][2] - mn1);
            sc[ni][3] = __expf(sc[ni][3] - mn1);
            rs0 += sc[ni][0] + sc[ni][1];
            rs1 += sc[ni][2] + sc[ni][3];
        }
        rs0 += __shfl_xor_sync(0xffffffffu, rs0, 1);
        rs0 += __shfl_xor_sync(0xffffffffu, rs0, 2);
        rs1 += __shfl_xor_sync(0xffffffffu, rs1, 1);
        rs1 += __shfl_xor_sync(0xffffffffu, rs1, 2);

        l0 = l0 * a0 + rs0;  m0 = mn0;
        l1 = l1 * a1 + rs1;  m1 = mn1;
        #pragma unroll
        for (int ni = 0; ni < 8; ni++) {
            o[ni][0] *= a0; o[ni][1] *= a0;
            o[ni][2] *= a1; o[ni][3] *= a1;
        }

        // ---- P to warp-private smem strip (tf32-rounded) ----
        float* Pw = Qs + (wid * 16) * 68;
        #pragma unroll
        for (int ni = 0; ni < 8; ni++) {
            *(float2*)&Pw[(qr    ) * 68 + ni * 8 + 2 * qc] =
                make_float2(to_tf32(sc[ni][0]), to_tf32(sc[ni][1]));
            *(float2*)&Pw[(qr + 8) * 68 + ni * 8 + 2 * qc] =
                make_float2(to_tf32(sc[ni][2]), to_tf32(sc[ni][3]));
        }
        __syncwarp();

        // ---- O += P V ----
        #pragma unroll
        for (int ks = 0; ks < 8; ks++) {
            const int k = ks * 8;
            uint32_t a[4];
            a[0] = __float_as_uint(Pw[(qr    ) * 68 + k + qc    ]);
            a[1] = __float_as_uint(Pw[(qr + 8) * 68 + k + qc    ]);
            a[2] = __float_as_uint(Pw[(qr    ) * 68 + k + 4 + qc]);
            a[3] = __float_as_uint(Pw[(qr + 8) * 68 + k + 4 + qc]);
            #pragma unroll
            for (int ni = 0; ni < 8; ni++) {
                uint32_t bf[2];
                bf[0] = __float_as_uint(V_[(k + qc    ) * 72 + ni * 8 + qr]);
                bf[1] = __float_as_uint(V_[(k + 4 + qc) * 72 + ni * 8 + qr]);
                mma_tf32(o[ni], a, bf);
            }
        }

        __syncthreads();   // all warps done with this K/V buffer
    }

    // ---- finalize + write out[b, t, h*64 + v] ----
    const float inv0 = 1.0f / l0;
    const float inv1 = 1.0f / l1;
    const int t0 = q0 + wid * 16 + qr;
    size_t base0 = ((size_t)b * NT + t0) * (NH * NDK) + h * NDK;
    size_t base1 = base0 + 8 * (size_t)(NH * NDK);
    #pragma unroll
    for (int ni = 0; ni < 8; ni++) {
        const int n = ni * 8 + 2 * qc;
        *(float2*)&out[base0 + n] = make_float2(o[ni][0] * inv0, o[ni][1] * inv0);
        *(float2*)&out[base1 + n] = make_float2(o[ni][2] * inv1, o[ni][3] * inv1);
    }
}

// ---------------------------------------------------------------------------
extern "C" void kernel_launch(void* const* d_in, const int* in_sizes, int n_in,
                              void* d_out, int out_size)
{
    (void)in_sizes; (void)n_in; (void)out_size;
    const float* x  = (const float*)d_in[0];
    const float* Wq = (const float*)d_in[1];
    const float* Wk = (const float*)d_in[2];
    const float* Wv = (const float*)d_in[3];
    float* out = (float*)d_out;

    cudaFuncSetAttribute(proj_mma,
                         cudaFuncAttributeMaxDynamicSharedMemorySize, PROJ_SMEM);
    cudaFuncSetAttribute(attn_mma,
                         cudaFuncAttributeMaxDynamicSharedMemorySize, ATT_SMEM);

    proj_mma<<<dim3(NB * NT / 128, NH, 3), 256, PROJ_SMEM>>>(x, Wq, Wk, Wv);

    attn_mma<<<dim3(NT / 128, NB * NH), 256, ATT_SMEM>>>(out);
}

// round 6
// speedup vs baseline: 3.0343x; 1.0333x over previous
#include <cuda_runtime.h>
#include <math.h>
#include <stdint.h>

#define NB 4
#define NT 2048
#define NDM 1024
#define NH 16
#define NDK 64

// Scratch for projected Q/K/V: [B,H,T,64] each (tf32-rounded values).
__device__ float g_q[NB*NH*NT*NDK];
__device__ float g_k[NB*NH*NT*NDK];
__device__ float g_v[NB*NH*NT*NDK];

__device__ __forceinline__ float to_tf32(float f) {
    float r; asm("cvt.rna.tf32.f32 %0, %1;" : "=f"(r) : "f"(f)); return r;
}
__device__ __forceinline__ void mma_tf32(float* c, const uint32_t* a, const uint32_t* b) {
    asm volatile("mma.sync.aligned.m16n8k8.row.col.f32.tf32.tf32.f32 "
                 "{%0,%1,%2,%3}, {%4,%5,%6,%7}, {%8,%9}, {%0,%1,%2,%3};"
                 : "+f"(c[0]), "+f"(c[1]), "+f"(c[2]), "+f"(c[3])
                 : "r"(a[0]), "r"(a[1]), "r"(a[2]), "r"(a[3]),
                   "r"(b[0]), "r"(b[1]));
}
__device__ __forceinline__ uint32_t smem_u32(const void* p) {
    uint32_t a;
    asm("{ .reg .u64 t; cvta.to.shared.u64 t, %1; cvt.u32.u64 %0, t; }"
        : "=r"(a) : "l"(p));
    return a;
}
#define CP_ASYNC16(dst, src) \
    asm volatile("cp.async.cg.shared.global [%0], [%1], 16;" \
                 :: "r"(dst), "l"(src) : "memory")
#define CP_COMMIT  asm volatile("cp.async.commit_group;" ::: "memory")
#define CP_WAIT(n) asm volatile("cp.async.wait_group %0;" :: "n"(n) : "memory")

// ---------------------------------------------------------------------------
// Projection GEMM v2 on mma.sync tf32.
// CTA: M=128 x N=128 (N spans 2 heads of one of Wq/Wk/Wv; z uniform per CTA
// since 8 n-tiles x 128 = 1024 = one z-slice), K=1024, BK=32, double-buffered
// smem with register prefetch. 8 warps (4 x 2), each a 32x64 tile = 2mi x 8ni
// m16n8k8 fragments, 64 mma per warp per stage. As[128][36], Bs[32][136]:
// both fragment LDS patterns conflict-free (4qr+qc and 8qc+qr).
// ---------------------------------------------------------------------------
#define P2_AS_STRIDE 36
#define P2_BS_STRIDE 136
#define P2_BS_OFF    (128 * P2_AS_STRIDE)                       // 4608
#define P2_STAGE     (P2_BS_OFF + 32 * P2_BS_STRIDE)            // 8960 floats
#define P2_SMEM      (2 * P2_STAGE * 4)                         // 71680 B

__global__ __launch_bounds__(256, 1) void proj_mma2(
    const float* __restrict__ x,
    const float* __restrict__ Wq,
    const float* __restrict__ Wk,
    const float* __restrict__ Wv)
{
    extern __shared__ float sm[];

    const int m0 = blockIdx.x * 128;
    const int by = blockIdx.y;           // 0..23
    const int z  = by >> 3;              // matrix select (uniform per CTA)
    const int h0 = (by & 7) * 2;         // first of 2 heads this CTA covers
    const float* W = ((z == 0) ? Wq : (z == 1) ? Wk : Wv)
                     + (size_t)h0 * NDM * NDK;
    float* outp    = ((z == 0) ? g_q : (z == 1) ? g_k : g_v);

    const int tid  = threadIdx.x;
    const int wid  = tid >> 5;
    const int lane = tid & 31;
    const int qr   = lane >> 2;
    const int qc   = lane & 3;
    const int wr   = wid >> 1;           // 0..3 : rows wr*32
    const int wc   = wid & 1;            // 0..1 : cols wc*64

    // Stage-invariant per-thread load indices.
    // A: 128x32 floats = 1024 float4, 4 per thread.
    int arow[4], acol[4];
    #pragma unroll
    for (int j = 0; j < 4; j++) {
        int q = tid + j * 256;
        arow[j] = q >> 3; acol[j] = (q & 7) * 4;
    }
    // B: 32x128 floats = 1024 float4, 4 per thread.
    int brow[4], bhead[4], bc[4], bsc[4];
    #pragma unroll
    for (int j = 0; j < 4; j++) {
        int q = tid + j * 256;
        brow[j] = q >> 5;
        int n4  = (q & 31) * 4;
        bhead[j] = n4 >> 6; bc[j] = n4 & 63; bsc[j] = n4;
    }

    float acc[2][8][4];
    #pragma unroll
    for (int mi = 0; mi < 2; mi++)
        #pragma unroll
        for (int ni = 0; ni < 8; ni++)
            #pragma unroll
            for (int v = 0; v < 4; v++) acc[mi][ni][v] = 0.0f;

    // ---- prologue: stage 0 ----
    {
        float* As = sm;
        float* Bs = sm + P2_BS_OFF;
        #pragma unroll
        for (int j = 0; j < 4; j++) {
            float4 v = *(const float4*)&x[(size_t)(m0 + arow[j]) * NDM + acol[j]];
            v.x = to_tf32(v.x); v.y = to_tf32(v.y);
            v.z = to_tf32(v.z); v.w = to_tf32(v.w);
            *(float4*)&As[arow[j] * P2_AS_STRIDE + acol[j]] = v;
        }
        #pragma unroll
        for (int j = 0; j < 4; j++) {
            float4 v = *(const float4*)&W[(size_t)bhead[j] * NDM * NDK
                                          + (size_t)brow[j] * NDK + bc[j]];
            v.x = to_tf32(v.x); v.y = to_tf32(v.y);
            v.z = to_tf32(v.z); v.w = to_tf32(v.w);
            *(float4*)&Bs[brow[j] * P2_BS_STRIDE + bsc[j]] = v;
        }
    }
    __syncthreads();

    // ---- main loop over 32 K-stages ----
    for (int s = 0; s < 32; s++) {
        float4 pa[4], pb[4];
        if (s + 1 < 32) {
            const int k1 = (s + 1) * 32;
            #pragma unroll
            for (int j = 0; j < 4; j++)
                pa[j] = *(const float4*)&x[(size_t)(m0 + arow[j]) * NDM + k1 + acol[j]];
            #pragma unroll
            for (int j = 0; j < 4; j++)
                pb[j] = *(const float4*)&W[(size_t)bhead[j] * NDM * NDK
                                           + (size_t)(k1 + brow[j]) * NDK + bc[j]];
        }

        const float* As = sm + (s & 1) * P2_STAGE;
        const float* Bs = As + P2_BS_OFF;
        #pragma unroll
        for (int ks = 0; ks < 4; ks++) {
            const int k = ks * 8;
            uint32_t af[2][4], bf[8][2];
            #pragma unroll
            for (int mi = 0; mi < 2; mi++) {
                const int rb = wr * 32 + mi * 16 + qr;
                af[mi][0] = __float_as_uint(As[(rb    ) * P2_AS_STRIDE + k + qc]);
                af[mi][1] = __float_as_uint(As[(rb + 8) * P2_AS_STRIDE + k + qc]);
                af[mi][2] = __float_as_uint(As[(rb    ) * P2_AS_STRIDE + k + 4 + qc]);
                af[mi][3] = __float_as_uint(As[(rb + 8) * P2_AS_STRIDE + k + 4 + qc]);
            }
            #pragma unroll
            for (int ni = 0; ni < 8; ni++) {
                const int cb = wc * 64 + ni * 8 + qr;
                bf[ni][0] = __float_as_uint(Bs[(k + qc    ) * P2_BS_STRIDE + cb]);
                bf[ni][1] = __float_as_uint(Bs[(k + 4 + qc) * P2_BS_STRIDE + cb]);
            }
            #pragma unroll
            for (int mi = 0; mi < 2; mi++)
                #pragma unroll
                for (int ni = 0; ni < 8; ni++)
                    mma_tf32(acc[mi][ni], af[mi], bf[ni]);
        }

        if (s + 1 < 32) {
            float* Asn = sm + ((s + 1) & 1) * P2_STAGE;
            float* Bsn = Asn + P2_BS_OFF;
            #pragma unroll
            for (int j = 0; j < 4; j++) {
                float4 v = pa[j];
                v.x = to_tf32(v.x); v.y = to_tf32(v.y);
                v.z = to_tf32(v.z); v.w = to_tf32(v.w);
                *(float4*)&Asn[arow[j] * P2_AS_STRIDE + acol[j]] = v;
            }
            #pragma unroll
            for (int j = 0; j < 4; j++) {
                float4 v = pb[j];
                v.x = to_tf32(v.x); v.y = to_tf32(v.y);
                v.z = to_tf32(v.z); v.w = to_tf32(v.w);
                *(float4*)&Bsn[brow[j] * P2_BS_STRIDE + bsc[j]] = v;
            }
        }
        __syncthreads();
    }

    // ---- epilogue: write out[((b*H+h)*T + t)*64 + c], tf32-rounded ----
    const int b     = m0 >> 11;
    const int tbase = m0 & 2047;
    #pragma unroll
    for (int mi = 0; mi < 2; mi++) {
        const int t0 = tbase + wr * 32 + mi * 16 + qr;
        #pragma unroll
        for (int ni = 0; ni < 8; ni++) {
            const int ncta = wc * 64 + ni * 8 + 2 * qc;   // 0..127 within CTA
            const int h    = h0 + (ncta >> 6);
            const int c    = ncta & 63;
            size_t base0 = (((size_t)(b * NH + h)) * NT + t0) * NDK + c;
            size_t base1 = base0 + 8 * NDK;
            *(float2*)&outp[base0] = make_float2(to_tf32(acc[mi][ni][0]),
                                                 to_tf32(acc[mi][ni][1]));
            *(float2*)&outp[base1] = make_float2(to_tf32(acc[mi][ni][2]),
                                                 to_tf32(acc[mi][ni][3]));
        }
    }
}

// ---------------------------------------------------------------------------
// Flash attention on mma.sync tf32 (unchanged from round 4).
// ---------------------------------------------------------------------------
#define ATT_SMEM (26624 * 4)

__global__ __launch_bounds__(256, 2) void attn_mma(float* __restrict__ out)
{
    extern __shared__ float sm[];
    float* Qs = sm;

    const int qt = 15 - (int)blockIdx.x;
    const int bh = blockIdx.y;
    const int b  = bh >> 4;
    const int h  = bh & 15;
    const int q0 = qt * 128;

    const float* qg = g_q + (size_t)bh * NT * NDK;
    const float* kg = g_k + (size_t)bh * NT * NDK;
    const float* vg = g_v + (size_t)bh * NT * NDK;

    const int tid  = threadIdx.x;
    const int wid  = tid >> 5;
    const int lane = tid & 31;
    const int qr   = lane >> 2;
    const int qc   = lane & 3;

    const uint32_t smb = smem_u32(sm);

    #pragma unroll
    for (int j = 0; j < 8; j++) {
        int q = tid + j * 256;
        int row = q >> 4, c4 = (q & 15) * 4;
        CP_ASYNC16(smb + (uint32_t)(row * 68 + c4) * 4,
                   qg + (size_t)(q0 + row) * NDK + c4);
    }
    CP_COMMIT;

    #pragma unroll
    for (int j = 0; j < 4; j++) {
        int q = tid + j * 256;
        int row = q >> 4, c4 = (q & 15) * 4;
        CP_ASYNC16(smb + (uint32_t)(8704 + row * 68 + c4) * 4,
                   kg + (size_t)row * NDK + c4);
        CP_ASYNC16(smb + (uint32_t)(17408 + row * 72 + c4) * 4,
                   vg + (size_t)row * NDK + c4);
    }
    CP_COMMIT;

    CP_WAIT(1);
    __syncthreads();

    uint32_t qf[8][4];
    {
        const float* Qw = Qs + (wid * 16) * 68;
        #pragma unroll
        for (int ks = 0; ks < 8; ks++) {
            const int k = ks * 8;
            qf[ks][0] = __float_as_uint(Qw[(qr    ) * 68 + k + qc    ] * 0.125f);
            qf[ks][1] = __float_as_uint(Qw[(qr + 8) * 68 + k + qc    ] * 0.125f);
            qf[ks][2] = __float_as_uint(Qw[(qr    ) * 68 + k + 4 + qc] * 0.125f);
            qf[ks][3] = __float_as_uint(Qw[(qr + 8) * 68 + k + 4 + qc] * 0.125f);
        }
    }

    float o[8][4];
    #pragma unroll
    for (int ni = 0; ni < 8; ni++)
        #pragma unroll
        for (int v = 0; v < 4; v++) o[ni][v] = 0.0f;
    float m0 = -INFINITY, m1 = -INFINITY, l0 = 0.0f, l1 = 0.0f;

    const int ntiles = 2 * qt + 2;

    for (int kt = 0; kt < ntiles; kt++) {
        if (kt + 1 < ntiles) {
            const int s1 = (kt + 1) * 64;
            const uint32_t kb = 8704  + ((kt + 1) & 1) * 4352;
            const uint32_t vb = 17408 + ((kt + 1) & 1) * 4608;
            #pragma unroll
            for (int j = 0; j < 4; j++) {
                int q = tid + j * 256;
                int row = q >> 4, c4 = (q & 15) * 4;
                CP_ASYNC16(smb + (kb + row * 68 + c4) * 4,
                           kg + (size_t)(s1 + row) * NDK + c4);
                CP_ASYNC16(smb + (vb + row * 72 + c4) * 4,
                           vg + (size_t)(s1 + row) * NDK + c4);
            }
            CP_COMMIT;
            CP_WAIT(1);
        } else {
            CP_WAIT(0);
        }
        __syncthreads();

        const float* K_ = sm + 8704  + (kt & 1) * 4352;
        const float* V_ = sm + 17408 + (kt & 1) * 4608;
        const int s0 = kt * 64;

        float sc[8][4];
        #pragma unroll
        for (int ni = 0; ni < 8; ni++)
            #pragma unroll
            for (int v = 0; v < 4; v++) sc[ni][v] = 0.0f;

        #pragma unroll
        for (int ni = 0; ni < 8; ni++) {
            const int cb = ni * 8 + qr;
            #pragma unroll
            for (int ks = 0; ks < 8; ks++) {
                const int k = ks * 8;
                uint32_t bf[2];
                bf[0] = __float_as_uint(K_[cb * 68 + k + qc    ]);
                bf[1] = __float_as_uint(K_[cb * 68 + k + 4 + qc]);
                mma_tf32(sc[ni], qf[ks], bf);
            }
        }

        if (kt >= 2 * qt) {
            const int r0g = q0 + wid * 16 + qr;
            const int r1g = r0g + 8;
            #pragma unroll
            for (int ni = 0; ni < 8; ni++) {
                const int c = s0 + ni * 8 + 2 * qc;
                if (c     > r0g) sc[ni][0] = -INFINITY;
                if (c + 1 > r0g) sc[ni][1] = -INFINITY;
                if (c     > r1g) sc[ni][2] = -INFINITY;
                if (c + 1 > r1g) sc[ni][3] = -INFINITY;
            }
        }

        float rmax0 = sc[0][0], rmax1 = sc[0][2];
        #pragma unroll
        for (int ni = 0; ni < 8; ni++) {
            rmax0 = fmaxf(rmax0, fmaxf(sc[ni][0], sc[ni][1]));
            rmax1 = fmaxf(rmax1, fmaxf(sc[ni][2], sc[ni][3]));
        }
        rmax0 = fmaxf(rmax0, __shfl_xor_sync(0xffffffffu, rmax0, 1));
        rmax0 = fmaxf(rmax0, __shfl_xor_sync(0xffffffffu, rmax0, 2));
        rmax1 = fmaxf(rmax1, __shfl_xor_sync(0xffffffffu, rmax1, 1));
        rmax1 = fmaxf(rmax1, __shfl_xor_sync(0xffffffffu, rmax1, 2));

        const float mn0 = fmaxf(m0, rmax0);
        const float mn1 = fmaxf(m1, rmax1);
        const float a0  = __expf(m0 - mn0);
        const float a1  = __expf(m1 - mn1);

        float rs0 = 0.0f, rs1 = 0.0f;
        #pragma unroll
        for (int ni = 0; ni < 8; ni++) {
            sc[ni][0] = __expf(sc[ni][0] - mn0);
            sc[ni][1] = __expf(sc[ni][1] - mn0);
            sc[ni][2] = __expf(sc[ni][2] - mn1);
            sc[ni][3] = __expf(sc[ni][3] - mn1);
            rs0 += sc[ni][0] + sc[ni][1];
            rs1 += sc[ni][2] + sc[ni][3];
        }
        rs0 += __shfl_xor_sync(0xffffffffu, rs0, 1);
        rs0 += __shfl_xor_sync(0xffffffffu, rs0, 2);
        rs1 += __shfl_xor_sync(0xffffffffu, rs1, 1);
        rs1 += __shfl_xor_sync(0xffffffffu, rs1, 2);

        l0 = l0 * a0 + rs0;  m0 = mn0;
        l1 = l1 * a1 + rs1;  m1 = mn1;
        #pragma unroll
        for (int ni = 0; ni < 8; ni++) {
            o[ni][0] *= a0; o[ni][1] *= a0;
            o[ni][2] *= a1; o[ni][3] *= a1;
        }

        float* Pw = Qs + (wid * 16) * 68;
        #pragma unroll
        for (int ni = 0; ni < 8; ni++) {
            *(float2*)&Pw[(qr    ) * 68 + ni * 8 + 2 * qc] =
                make_float2(to_tf32(sc[ni][0]), to_tf32(sc[ni][1]));
            *(float2*)&Pw[(qr + 8) * 68 + ni * 8 + 2 * qc] =
                make_float2(to_tf32(sc[ni][2]), to_tf32(sc[ni][3]));
        }
        __syncwarp();

        #pragma unroll
        for (int ks = 0; ks < 8; ks++) {
            const int k = ks * 8;
            uint32_t a[4];
            a[0] = __float_as_uint(Pw[(qr    ) * 68 + k + qc    ]);
            a[1] = __float_as_uint(Pw[(qr + 8) * 68 + k + qc    ]);
            a[2] = __float_as_uint(Pw[(qr    ) * 68 + k + 4 + qc]);
            a[3] = __float_as_uint(Pw[(qr + 8) * 68 + k + 4 + qc]);
            #pragma unroll
            for (int ni = 0; ni < 8; ni++) {
                uint32_t bf[2];
                bf[0] = __float_as_uint(V_[(k + qc    ) * 72 + ni * 8 + qr]);
                bf[1] = __float_as_uint(V_[(k + 4 + qc) * 72 + ni * 8 + qr]);
                mma_tf32(o[ni], a, bf);
            }
        }

        __syncthreads();
    }

    const float inv0 = 1.0f / l0;
    const float inv1 = 1.0f / l1;
    const int t0 = q0 + wid * 16 + qr;
    size_t base0 = ((size_t)b * NT + t0) * (NH * NDK) + h * NDK;
    size_t base1 = base0 + 8 * (size_t)(NH * NDK);
    #pragma unroll
    for (int ni = 0; ni < 8; ni++) {
        const int n = ni * 8 + 2 * qc;
        *(float2*)&out[base0 + n] = make_float2(o[ni][0] * inv0, o[ni][1] * inv0);
        *(float2*)&out[base1 + n] = make_float2(o[ni][2] * inv1, o[ni][3] * inv1);
    }
}

// ---------------------------------------------------------------------------
extern "C" void kernel_launch(void* const* d_in, const int* in_sizes, int n_in,
                              void* d_out, int out_size)
{
    (void)in_sizes; (void)n_in; (void)out_size;
    const float* x  = (const float*)d_in[0];
    const float* Wq = (const float*)d_in[1];
    const float* Wk = (const float*)d_in[2];
    const float* Wv = (const float*)d_in[3];
    float* out = (float*)d_out;

    cudaFuncSetAttribute(proj_mma2,
                         cudaFuncAttributeMaxDynamicSharedMemorySize, P2_SMEM);
    cudaFuncSetAttribute(attn_mma,
                         cudaFuncAttributeMaxDynamicSharedMemorySize, ATT_SMEM);

    proj_mma2<<<dim3(NB * NT / 128, 24), 256, P2_SMEM>>>(x, Wq, Wk, Wv);

    attn_mma<<<dim3(NT / 128, NB * NH), 256, ATT_SMEM>>>(out);
}

// round 8
// speedup vs baseline: 5.8685x; 1.9340x over previous
#include <cuda_runtime.h>
#include <cuda_fp16.h>
#include <math.h>
#include <stdint.h>

#define NB 4
#define NT 2048
#define NDM 1024
#define NH 16
#define NDK 64

// fp16 staging buffers
__device__ __half g_xh[NB*NT*NDM];        // x in fp16            [b*t][d]
__device__ __half g_wth[3*NH*NDK*NDM];    // W fp16 transposed    [z*1024+n][d]
__device__ __half g_qh[NB*NH*NT*NDK];     // Q*0.125 fp16         [bh][t][d]
__device__ __half g_kh[NB*NH*NT*NDK];     // K fp16               [bh][t][d]
__device__ __half g_vt[NB*NH*NDK*NT];     // V fp16 TRANSPOSED    [bh][d][t]

__device__ __forceinline__ void mma_f16(float* c, const uint32_t* a, const uint32_t* b) {
    asm volatile("mma.sync.aligned.m16n8k16.row.col.f32.f16.f16.f32 "
                 "{%0,%1,%2,%3}, {%4,%5,%6,%7}, {%8,%9}, {%0,%1,%2,%3};"
                 : "+f"(c[0]), "+f"(c[1]), "+f"(c[2]), "+f"(c[3])
                 : "r"(a[0]), "r"(a[1]), "r"(a[2]), "r"(a[3]),
                   "r"(b[0]), "r"(b[1]));
}
__device__ __forceinline__ uint32_t smem_u32(const void* p) {
    uint32_t a;
    asm("{ .reg .u64 t; cvta.to.shared.u64 t, %1; cvt.u32.u64 %0, t; }"
        : "=r"(a) : "l"(p));
    return a;
}
#define CP_ASYNC16(dst, src) \
    asm volatile("cp.async.cg.shared.global [%0], [%1], 16;" \
                 :: "r"(dst), "l"(src) : "memory")
#define CP_COMMIT  asm volatile("cp.async.commit_group;" ::: "memory")
#define CP_WAIT(n) asm volatile("cp.async.wait_group %0;" :: "n"(n) : "memory")

// ---------------------------------------------------------------------------
// Pre-pass 1: x -> fp16
// ---------------------------------------------------------------------------
__global__ __launch_bounds__(256) void convert_x(const float* __restrict__ x)
{
    const int i = ((int)blockIdx.x * 256 + (int)threadIdx.x) * 4;
    float4 v = *(const float4*)&x[i];
    *(__half2*)&g_xh[i]     = __floats2half2_rn(v.x, v.y);
    *(__half2*)&g_xh[i + 2] = __floats2half2_rn(v.z, v.w);
}

// ---------------------------------------------------------------------------
// Pre-pass 2: W[h][d][n] -> Wt fp16 [z*1024 + h*64 + n][d]
// ---------------------------------------------------------------------------
__global__ __launch_bounds__(256) void convert_w(
    const float* __restrict__ Wq, const float* __restrict__ Wk,
    const float* __restrict__ Wv)
{
    __shared__ float tile[32][33];
    const int zh = blockIdx.z;               // 0..47
    const int z = zh >> 4, h = zh & 15;
    const float* W = (z == 0 ? Wq : z == 1 ? Wk : Wv) + (size_t)h * NDM * NDK;
    const int d0 = blockIdx.x * 32;
    const int n0 = blockIdx.y * 32;
    const int tx = threadIdx.x, ty = threadIdx.y;   // (32, 8)

    #pragma unroll
    for (int j = 0; j < 4; j++)
        tile[ty + j * 8][tx] = W[(size_t)(d0 + ty + j * 8) * NDK + n0 + tx];
    __syncthreads();
    __half* dst = g_wth + ((size_t)(z * NH + h) * NDK) * NDM;
    #pragma unroll
    for (int j = 0; j < 4; j++)
        dst[(size_t)(n0 + ty + j * 8) * NDM + d0 + tx] =
            __float2half_rn(tile[tx][ty + j * 8]);
}

// ---------------------------------------------------------------------------
// Projection GEMM on fp16 m16n8k16. CTA: M=128 x N=128 x K=1024, BK=64,
// cp.async double buffer, 8 warps (4x2), warp tile 32x64 = 2mi x 8ni,
// 4 k-steps of 16 per stage. Tiles stride 72 halves (144B) -> LDS pattern
// bank = (4qr + qc) mod 32, conflict-free.
// ---------------------------------------------------------------------------
#define PJ_STRIDE 72
#define PJ_TILE   (128 * PJ_STRIDE)          // 9216 halves per operand tile
#define PJ_STAGE  (2 * PJ_TILE)              // halves per stage (A + B)
#define PJ_SMEM   (2 * PJ_STAGE * 2)         // bytes = 73728

__global__ __launch_bounds__(256, 2) void proj_h()
{
    extern __shared__ __half smh[];
    const uint32_t smb = smem_u32(smh);

    const int m0 = blockIdx.x * 128;
    const int by = blockIdx.y;               // 0..23
    const int z  = by >> 3;
    const int n0 = (by & 7) * 128;
    const __half* wt = g_wth + (size_t)(z * 1024 + n0) * NDM;

    const int tid  = threadIdx.x;
    const int wid  = tid >> 5;
    const int lane = tid & 31;
    const int qr   = lane >> 2;
    const int qc   = lane & 3;
    const int wr   = wid >> 1;
    const int wc   = wid & 1;

    const int row_ = tid >> 3;               // 0..31 (+32j)
    const int ch_  = (tid & 7) * 8;          // half offset of 16B chunk

    float acc[2][8][4];
    #pragma unroll
    for (int mi = 0; mi < 2; mi++)
        #pragma unroll
        for (int ni = 0; ni < 8; ni++)
            #pragma unroll
            for (int v = 0; v < 4; v++) acc[mi][ni][v] = 0.0f;

    // prologue: stage 0 (k0 = 0)
    #pragma unroll
    for (int j = 0; j < 4; j++) {
        int row = row_ + j * 32;
        CP_ASYNC16(smb + (uint32_t)(row * PJ_STRIDE + ch_) * 2,
                   g_xh + (size_t)(m0 + row) * NDM + ch_);
        CP_ASYNC16(smb + (uint32_t)(PJ_TILE + row * PJ_STRIDE + ch_) * 2,
                   wt + (size_t)row * NDM + ch_);
    }
    CP_COMMIT;

    for (int s = 0; s < 16; s++) {
        if (s + 1 < 16) {
            const int k1 = (s + 1) * 64;
            const uint32_t sb = (uint32_t)(((s + 1) & 1) * PJ_STAGE);
            #pragma unroll
            for (int j = 0; j < 4; j++) {
                int row = row_ + j * 32;
                CP_ASYNC16(smb + (sb + row * PJ_STRIDE + ch_) * 2,
                           g_xh + (size_t)(m0 + row) * NDM + k1 + ch_);
                CP_ASYNC16(smb + (sb + PJ_TILE + row * PJ_STRIDE + ch_) * 2,
                           wt + (size_t)row * NDM + k1 + ch_);
            }
            CP_COMMIT;
            CP_WAIT(1);
        } else {
            CP_WAIT(0);
        }
        __syncthreads();

        const __half* As = smh + (s & 1) * PJ_STAGE;
        const __half* Bs = As + PJ_TILE;
        #pragma unroll
        for (int ks = 0; ks < 4; ks++) {
            const int k = ks * 16 + 2 * qc;
            uint32_t af[2][4], bf[8][2];
            #pragma unroll
            for (int mi = 0; mi < 2; mi++) {
                const int rb = wr * 32 + mi * 16 + qr;
                const __half* p = As + rb * PJ_STRIDE + k;
                af[mi][0] = *(const uint32_t*)(p);
                af[mi][1] = *(const uint32_t*)(p + 8 * PJ_STRIDE);
                af[mi][2] = *(const uint32_t*)(p + 8);
                af[mi][3] = *(const uint32_t*)(p + 8 * PJ_STRIDE + 8);
            }
            #pragma unroll
            for (int ni = 0; ni < 8; ni++) {
                const int cb = wc * 64 + ni * 8 + qr;
                const __half* p = Bs + cb * PJ_STRIDE + k;
                bf[ni][0] = *(const uint32_t*)(p);
                bf[ni][1] = *(const uint32_t*)(p + 8);
            }
            #pragma unroll
            for (int mi = 0; mi < 2; mi++)
                #pragma unroll
                for (int ni = 0; ni < 8; ni++)
                    mma_f16(acc[mi][ni], af[mi], bf[ni]);
        }
        __syncthreads();
    }

    // epilogue
    const int b     = m0 >> 11;
    const int tbase = m0 & 2047;
    #pragma unroll
    for (int mi = 0; mi < 2; mi++) {
        const int t0 = tbase + wr * 32 + mi * 16 + qr;
        #pragma unroll
        for (int ni = 0; ni < 8; ni++) {
            const int ncta = wc * 64 + ni * 8 + 2 * qc;
            const int ng   = n0 + ncta;
            const int h    = ng >> 6;
            const int d    = ng & 63;
            const size_t bh = (size_t)(b * NH + h);
            if (z == 0) {          // Q, pre-scaled by 1/8
                *(__half2*)&g_qh[(bh * NT + t0) * NDK + d] =
                    __floats2half2_rn(acc[mi][ni][0] * 0.125f, acc[mi][ni][1] * 0.125f);
                *(__half2*)&g_qh[(bh * NT + t0 + 8) * NDK + d] =
                    __floats2half2_rn(acc[mi][ni][2] * 0.125f, acc[mi][ni][3] * 0.125f);
            } else if (z == 1) {   // K
                *(__half2*)&g_kh[(bh * NT + t0) * NDK + d] =
                    __floats2half2_rn(acc[mi][ni][0], acc[mi][ni][1]);
                *(__half2*)&g_kh[(bh * NT + t0 + 8) * NDK + d] =
                    __floats2half2_rn(acc[mi][ni][2], acc[mi][ni][3]);
            } else {               // V transposed [bh][d][t]
                g_vt[(bh * NDK + d    ) * NT + t0    ] = __float2half_rn(acc[mi][ni][0]);
                g_vt[(bh * NDK + d + 1) * NT + t0    ] = __float2half_rn(acc[mi][ni][1]);
                g_vt[(bh * NDK + d    ) * NT + t0 + 8] = __float2half_rn(acc[mi][ni][2]);
                g_vt[(bh * NDK + d + 1) * NT + t0 + 8] = __float2half_rn(acc[mi][ni][3]);
            }
        }
    }
}

// ---------------------------------------------------------------------------
// Flash attention on fp16 m16n8k16. CTA: 128-q tile x (b,h); 8 warps each a
// 16x64 strip; 64-key tiles double-buffered via cp.async.
// Smem halves: QP 128x72 | K 2x64x72 | V 2x64x72 = 27648 (55296 B).
// ---------------------------------------------------------------------------
#define AT_STRIDE 72
#define AT_KOFF   (128 * AT_STRIDE)            // 9216
#define AT_VOFF   (AT_KOFF + 2 * 64 * AT_STRIDE)   // 18432
#define AT_SMEM   ((AT_VOFF + 2 * 64 * AT_STRIDE) * 2)  // 55296 B

__global__ __launch_bounds__(256, 2) void attn_h(float* __restrict__ out)
{
    extern __shared__ __half smh[];
    const uint32_t smb = smem_u32(smh);

    const int qt = 15 - (int)blockIdx.x;
    const int bh = blockIdx.y;
    const int b  = bh >> 4;
    const int h  = bh & 15;
    const int q0 = qt * 128;

    const __half* qg = g_qh + (size_t)bh * NT * NDK;
    const __half* kg = g_kh + (size_t)bh * NT * NDK;
    const __half* vg = g_vt + (size_t)bh * NDK * NT;

    const int tid  = threadIdx.x;
    const int wid  = tid >> 5;
    const int lane = tid & 31;
    const int qr   = lane >> 2;
    const int qc   = lane & 3;

    const int row_ = tid >> 3;           // 0..31
    const int ch_  = (tid & 7) * 8;

    // Q tile (group A)
    #pragma unroll
    for (int j = 0; j < 4; j++) {
        int row = row_ + j * 32;
        CP_ASYNC16(smb + (uint32_t)(row * AT_STRIDE + ch_) * 2,
                   qg + (size_t)(q0 + row) * NDK + ch_);
    }
    CP_COMMIT;

    // K/V tile 0 (group B)
    #pragma unroll
    for (int j = 0; j < 2; j++) {
        int row = row_ + j * 32;
        CP_ASYNC16(smb + (uint32_t)(AT_KOFF + row * AT_STRIDE + ch_) * 2,
                   kg + (size_t)row * NDK + ch_);
        CP_ASYNC16(smb + (uint32_t)(AT_VOFF + row * AT_STRIDE + ch_) * 2,
                   vg + (size_t)row * NT + ch_);
    }
    CP_COMMIT;

    CP_WAIT(1);
    __syncthreads();

    // Q fragments (already scaled by 1/8 at projection)
    uint32_t qf[4][4];
    {
        const __half* Qw = smh + (wid * 16) * AT_STRIDE;
        #pragma unroll
        for (int ks = 0; ks < 4; ks++) {
            const __half* p = Qw + qr * AT_STRIDE + ks * 16 + 2 * qc;
            qf[ks][0] = *(const uint32_t*)(p);
            qf[ks][1] = *(const uint32_t*)(p + 8 * AT_STRIDE);
            qf[ks][2] = *(const uint32_t*)(p + 8);
            qf[ks][3] = *(const uint32_t*)(p + 8 * AT_STRIDE + 8);
        }
    }

    float o[8][4];
    #pragma unroll
    for (int ni = 0; ni < 8; ni++)
        #pragma unroll
        for (int v = 0; v < 4; v++) o[ni][v] = 0.0f;
    float m0 = -INFINITY, m1 = -INFINITY, l0 = 0.0f, l1 = 0.0f;

    const int ntiles = 2 * qt + 2;

    for (int kt = 0; kt < ntiles; kt++) {
        if (kt + 1 < ntiles) {
            const int s1 = (kt + 1) * 64;
            const uint32_t kb = AT_KOFF + ((kt + 1) & 1) * 64 * AT_STRIDE;
            const uint32_t vb = AT_VOFF + ((kt + 1) & 1) * 64 * AT_STRIDE;
            #pragma unroll
            for (int j = 0; j < 2; j++) {
                int row = row_ + j * 32;
                CP_ASYNC16(smb + (kb + row * AT_STRIDE + ch_) * 2,
                           kg + (size_t)(s1 + row) * NDK + ch_);
                CP_ASYNC16(smb + (vb + row * AT_STRIDE + ch_) * 2,
                           vg + (size_t)row * NT + s1 + ch_);
            }
            CP_COMMIT;
            CP_WAIT(1);
        } else {
            CP_WAIT(0);
        }
        __syncthreads();

        const __half* K_ = smh + AT_KOFF + (kt & 1) * 64 * AT_STRIDE;
        const __half* V_ = smh + AT_VOFF + (kt & 1) * 64 * AT_STRIDE;
        const int s0 = kt * 64;

        // S = (Q/8) K^T
        float sc[8][4];
        #pragma unroll
        for (int ni = 0; ni < 8; ni++)
            #pragma unroll
            for (int v = 0; v < 4; v++) sc[ni][v] = 0.0f;

        #pragma unroll
        for (int ni = 0; ni < 8; ni++) {
            const __half* kp = K_ + (ni * 8 + qr) * AT_STRIDE + 2 * qc;
            #pragma unroll
            for (int ks = 0; ks < 4; ks++) {
                uint32_t bf[2];
                bf[0] = *(const uint32_t*)(kp + ks * 16);
                bf[1] = *(const uint32_t*)(kp + ks * 16 + 8);
                mma_f16(sc[ni], qf[ks], bf);
            }
        }

        // causal mask (diagonal-overlap tiles only)
        if (kt >= 2 * qt) {
            const int r0g = q0 + wid * 16 + qr;
            const int r1g = r0g + 8;
            #pragma unroll
            for (int ni = 0; ni < 8; ni++) {
                const int c = s0 + ni * 8 + 2 * qc;
                if (c     > r0g) sc[ni][0] = -INFINITY;
                if (c + 1 > r0g) sc[ni][1] = -INFINITY;
                if (c     > r1g) sc[ni][2] = -INFINITY;
                if (c + 1 > r1g) sc[ni][3] = -INFINITY;
            }
        }

        // online softmax
        float rmax0 = sc[0][0], rmax1 = sc[0][2];
        #pragma unroll
        for (int ni = 0; ni < 8; ni++) {
            rmax0 = fmaxf(rmax0, fmaxf(sc[ni][0], sc[ni][1]));
            rmax1 = fmaxf(rmax1, fmaxf(sc[ni][2], sc[ni][3]));
        }
        rmax0 = fmaxf(rmax0, __shfl_xor_sync(0xffffffffu, rmax0, 1));
        rmax0 = fmaxf(rmax0, __shfl_xor_sync(0xffffffffu, rmax0, 2));
        rmax1 = fmaxf(rmax1, __shfl_xor_sync(0xffffffffu, rmax1, 1));
        rmax1 = fmaxf(rmax1, __shfl_xor_sync(0xffffffffu, rmax1, 2));

        const float mn0 = fmaxf(m0, rmax0);
        const float mn1 = fmaxf(m1, rmax1);
        const float a0  = __expf(m0 - mn0);
        const float a1  = __expf(m1 - mn1);

        float rs0 = 0.0f, rs1 = 0.0f;
        #pragma unroll
        for (int ni = 0; ni < 8; ni++) {
            sc[ni][0] = __expf(sc[ni][0] - mn0);
            sc[ni][1] = __expf(sc[ni][1] - mn0);
            sc[ni][2] = __expf(sc[ni][2] - mn1);
            sc[ni][3] = __expf(sc[ni][3] - mn1);
            rs0 += sc[ni][0] + sc[ni][1];
            rs1 += sc[ni][2] + sc[ni][3];
        }
        rs0 += __shfl_xor_sync(0xffffffffu, rs0, 1);
        rs0 += __shfl_xor_sync(0xffffffffu, rs0, 2);
        rs1 += __shfl_xor_sync(0xffffffffu, rs1, 1);
        rs1 += __shfl_xor_sync(0xffffffffu, rs1, 2);

        l0 = l0 * a0 + rs0;  m0 = mn0;
        l1 = l1 * a1 + rs1;  m1 = mn1;
        #pragma unroll
        for (int ni = 0; ni < 8; ni++) {
            o[ni][0] *= a0; o[ni][1] *= a0;
            o[ni][2] *= a1; o[ni][3] *= a1;
        }

        // P -> warp-private fp16 strip (over Q region)
        __half* Pw = smh + (wid * 16) * AT_STRIDE;
        #pragma unroll
        for (int ni = 0; ni < 8; ni++) {
            const int col = ni * 8 + 2 * qc;
            *(__half2*)&Pw[(qr    ) * AT_STRIDE + col] =
                __floats2half2_rn(sc[ni][0], sc[ni][1]);
            *(__half2*)&Pw[(qr + 8) * AT_STRIDE + col] =
                __floats2half2_rn(sc[ni][2], sc[ni][3]);
        }
        __syncwarp();

        // O += P V   (B = V^T tile, [d][s] with s contiguous)
        #pragma unroll
        for (int ks = 0; ks < 4; ks++) {
            const __half* pp = Pw + qr * AT_STRIDE + ks * 16 + 2 * qc;
            uint32_t a[4];
            a[0] = *(const uint32_t*)(pp);
            a[1] = *(const uint32_t*)(pp + 8 * AT_STRIDE);
            a[2] = *(const uint32_t*)(pp + 8);
            a[3] = *(const uint32_t*)(pp + 8 * AT_STRIDE + 8);
            #pragma unroll
            for (int ni = 0; ni < 8; ni++) {
                const __half* vp = V_ + (ni * 8 + qr) * AT_STRIDE + ks * 16 + 2 * qc;
                uint32_t bf[2];
                bf[0] = *(const uint32_t*)(vp);
                bf[1] = *(const uint32_t*)(vp + 8);
                mma_f16(o[ni], a, bf);
            }
        }

        __syncthreads();
    }

    // finalize + write out[b, t, h*64 + v]  (fp32)
    const float inv0 = 1.0f / l0;
    const float inv1 = 1.0f / l1;
    const int t0 = q0 + wid * 16 + qr;
    size_t base0 = ((size_t)b * NT + t0) * (NH * NDK) + h * NDK;
    size_t base1 = base0 + 8 * (size_t)(NH * NDK);
    #pragma unroll
    for (int ni = 0; ni < 8; ni++) {
        const int n = ni * 8 + 2 * qc;
        *(float2*)&out[base0 + n] = make_float2(o[ni][0] * inv0, o[ni][1] * inv0);
        *(float2*)&out[base1 + n] = make_float2(o[ni][2] * inv1, o[ni][3] * inv1);
    }
}

// ---------------------------------------------------------------------------
extern "C" void kernel_launch(void* const* d_in, const int* in_sizes, int n_in,
                              void* d_out, int out_size)
{
    (void)in_sizes; (void)n_in; (void)out_size;
    const float* x  = (const float*)d_in[0];
    const float* Wq = (const float*)d_in[1];
    const float* Wk = (const float*)d_in[2];
    const float* Wv = (const float*)d_in[3];
    float* out = (float*)d_out;

    cudaFuncSetAttribute(proj_h,
                         cudaFuncAttributeMaxDynamicSharedMemorySize, PJ_SMEM);
    cudaFuncSetAttribute(attn_h,
                         cudaFuncAttributeMaxDynamicSharedMemorySize, AT_SMEM);

    convert_x<<<NB * NT * NDM / 1024, 256>>>(x);
    convert_w<<<dim3(NDM / 32, NDK / 32, 48), dim3(32, 8)>>>(Wq, Wk, Wv);

    proj_h<<<dim3(NB * NT / 128, 24), 256, PJ_SMEM>>>();

    attn_h<<<dim3(NT / 128, NB * NH), 256, AT_SMEM>>>(out);
}

// round 9
// speedup vs baseline: 6.2474x; 1.0646x over previous
#include <cuda_runtime.h>
#include <cuda_fp16.h>
#include <math.h>
#include <stdint.h>

#define NB 4
#define NT 2048
#define NDM 1024
#define NH 16
#define NDK 64

// fp16 staging buffers
__device__ __half g_xh[NB*NT*NDM];        // x in fp16            [b*t][d]
__device__ __half g_wth[3*NH*NDK*NDM];    // W fp16 transposed    [z*1024+n][d]
__device__ __half g_qh[NB*NH*NT*NDK];     // Q*0.125*log2e fp16   [bh][t][d]
__device__ __half g_kh[NB*NH*NT*NDK];     // K fp16               [bh][t][d]
__device__ __half g_vt[NB*NH*NDK*NT];     // V fp16 TRANSPOSED    [bh][d][t]

__device__ __forceinline__ void mma_f16(float* c, const uint32_t* a, const uint32_t* b) {
    asm volatile("mma.sync.aligned.m16n8k16.row.col.f32.f16.f16.f32 "
                 "{%0,%1,%2,%3}, {%4,%5,%6,%7}, {%8,%9}, {%0,%1,%2,%3};"
                 : "+f"(c[0]), "+f"(c[1]), "+f"(c[2]), "+f"(c[3])
                 : "r"(a[0]), "r"(a[1]), "r"(a[2]), "r"(a[3]),
                   "r"(b[0]), "r"(b[1]));
}
__device__ __forceinline__ void ldsm_x4(uint32_t* d, uint32_t addr) {
    asm volatile("ldmatrix.sync.aligned.m8n8.x4.shared.b16 {%0,%1,%2,%3}, [%4];"
                 : "=r"(d[0]), "=r"(d[1]), "=r"(d[2]), "=r"(d[3]) : "r"(addr));
}
__device__ __forceinline__ uint32_t smem_u32(const void* p) {
    uint32_t a;
    asm("{ .reg .u64 t; cvta.to.shared.u64 t, %1; cvt.u32.u64 %0, t; }"
        : "=r"(a) : "l"(p));
    return a;
}
__device__ __forceinline__ uint32_t pack_h2(float lo, float hi) {
    __half2 h = __floats2half2_rn(lo, hi);
    return *(uint32_t*)&h;
}
#define CP_ASYNC16(dst, src) \
    asm volatile("cp.async.cg.shared.global [%0], [%1], 16;" \
                 :: "r"(dst), "l"(src) : "memory")
#define CP_COMMIT  asm volatile("cp.async.commit_group;" ::: "memory")
#define CP_WAIT(n) asm volatile("cp.async.wait_group %0;" :: "n"(n) : "memory")

// ---------------------------------------------------------------------------
// Pre-pass 1: x -> fp16
// ---------------------------------------------------------------------------
__global__ __launch_bounds__(256) void convert_x(const float* __restrict__ x)
{
    const int i = ((int)blockIdx.x * 256 + (int)threadIdx.x) * 4;
    float4 v = *(const float4*)&x[i];
    *(__half2*)&g_xh[i]     = __floats2half2_rn(v.x, v.y);
    *(__half2*)&g_xh[i + 2] = __floats2half2_rn(v.z, v.w);
}

// ---------------------------------------------------------------------------
// Pre-pass 2: W[h][d][n] -> Wt fp16 [z*1024 + h*64 + n][d]
// ---------------------------------------------------------------------------
__global__ __launch_bounds__(256) void convert_w(
    const float* __restrict__ Wq, const float* __restrict__ Wk,
    const float* __restrict__ Wv)
{
    __shared__ float tile[32][33];
    const int zh = blockIdx.z;
    const int z = zh >> 4, h = zh & 15;
    const float* W = (z == 0 ? Wq : z == 1 ? Wk : Wv) + (size_t)h * NDM * NDK;
    const int d0 = blockIdx.x * 32;
    const int n0 = blockIdx.y * 32;
    const int tx = threadIdx.x, ty = threadIdx.y;

    #pragma unroll
    for (int j = 0; j < 4; j++)
        tile[ty + j * 8][tx] = W[(size_t)(d0 + ty + j * 8) * NDK + n0 + tx];
    __syncthreads();
    __half* dst = g_wth + ((size_t)(z * NH + h) * NDK) * NDM;
    #pragma unroll
    for (int j = 0; j < 4; j++)
        dst[(size_t)(n0 + ty + j * 8) * NDM + d0 + tx] =
            __float2half_rn(tile[tx][ty + j * 8]);
}

// ---------------------------------------------------------------------------
// Projection GEMM on fp16 m16n8k16 (unchanged except Q scale = 0.125*log2e).
// ---------------------------------------------------------------------------
#define PJ_STRIDE 72
#define PJ_TILE   (128 * PJ_STRIDE)
#define PJ_STAGE  (2 * PJ_TILE)
#define PJ_SMEM   (2 * PJ_STAGE * 2)

__global__ __launch_bounds__(256, 2) void proj_h()
{
    extern __shared__ __half smh[];
    const uint32_t smb = smem_u32(smh);

    const int m0 = blockIdx.x * 128;
    const int by = blockIdx.y;
    const int z  = by >> 3;
    const int n0 = (by & 7) * 128;
    const __half* wt = g_wth + (size_t)(z * 1024 + n0) * NDM;

    const int tid  = threadIdx.x;
    const int wid  = tid >> 5;
    const int lane = tid & 31;
    const int qr   = lane >> 2;
    const int qc   = lane & 3;
    const int wr   = wid >> 1;
    const int wc   = wid & 1;

    const int row_ = tid >> 3;
    const int ch_  = (tid & 7) * 8;

    float acc[2][8][4];
    #pragma unroll
    for (int mi = 0; mi < 2; mi++)
        #pragma unroll
        for (int ni = 0; ni < 8; ni++)
            #pragma unroll
            for (int v = 0; v < 4; v++) acc[mi][ni][v] = 0.0f;

    #pragma unroll
    for (int j = 0; j < 4; j++) {
        int row = row_ + j * 32;
        CP_ASYNC16(smb + (uint32_t)(row * PJ_STRIDE + ch_) * 2,
                   g_xh + (size_t)(m0 + row) * NDM + ch_);
        CP_ASYNC16(smb + (uint32_t)(PJ_TILE + row * PJ_STRIDE + ch_) * 2,
                   wt + (size_t)row * NDM + ch_);
    }
    CP_COMMIT;

    for (int s = 0; s < 16; s++) {
        if (s + 1 < 16) {
            const int k1 = (s + 1) * 64;
            const uint32_t sb = (uint32_t)(((s + 1) & 1) * PJ_STAGE);
            #pragma unroll
            for (int j = 0; j < 4; j++) {
                int row = row_ + j * 32;
                CP_ASYNC16(smb + (sb + row * PJ_STRIDE + ch_) * 2,
                           g_xh + (size_t)(m0 + row) * NDM + k1 + ch_);
                CP_ASYNC16(smb + (sb + PJ_TILE + row * PJ_STRIDE + ch_) * 2,
                           wt + (size_t)row * NDM + k1 + ch_);
            }
            CP_COMMIT;
            CP_WAIT(1);
        } else {
            CP_WAIT(0);
        }
        __syncthreads();

        const __half* As = smh + (s & 1) * PJ_STAGE;
        const __half* Bs = As + PJ_TILE;
        #pragma unroll
        for (int ks = 0; ks < 4; ks++) {
            const int k = ks * 16 + 2 * qc;
            uint32_t af[2][4], bf[8][2];
            #pragma unroll
            for (int mi = 0; mi < 2; mi++) {
                const int rb = wr * 32 + mi * 16 + qr;
                const __half* p = As + rb * PJ_STRIDE + k;
                af[mi][0] = *(const uint32_t*)(p);
                af[mi][1] = *(const uint32_t*)(p + 8 * PJ_STRIDE);
                af[mi][2] = *(const uint32_t*)(p + 8);
                af[mi][3] = *(const uint32_t*)(p + 8 * PJ_STRIDE + 8);
            }
            #pragma unroll
            for (int ni = 0; ni < 8; ni++) {
                const int cb = wc * 64 + ni * 8 + qr;
                const __half* p = Bs + cb * PJ_STRIDE + k;
                bf[ni][0] = *(const uint32_t*)(p);
                bf[ni][1] = *(const uint32_t*)(p + 8);
            }
            #pragma unroll
            for (int mi = 0; mi < 2; mi++)
                #pragma unroll
                for (int ni = 0; ni < 8; ni++)
                    mma_f16(acc[mi][ni], af[mi], bf[ni]);
        }
        __syncthreads();
    }

    const float QSC = 0.125f * 1.44269504088896340736f;   // 1/8 * log2(e)
    const int b     = m0 >> 11;
    const int tbase = m0 & 2047;
    #pragma unroll
    for (int mi = 0; mi < 2; mi++) {
        const int t0 = tbase + wr * 32 + mi * 16 + qr;
        #pragma unroll
        for (int ni = 0; ni < 8; ni++) {
            const int ncta = wc * 64 + ni * 8 + 2 * qc;
            const int ng   = n0 + ncta;
            const int h    = ng >> 6;
            const int d    = ng & 63;
            const size_t bh = (size_t)(b * NH + h);
            if (z == 0) {
                *(__half2*)&g_qh[(bh * NT + t0) * NDK + d] =
                    __floats2half2_rn(acc[mi][ni][0] * QSC, acc[mi][ni][1] * QSC);
                *(__half2*)&g_qh[(bh * NT + t0 + 8) * NDK + d] =
                    __floats2half2_rn(acc[mi][ni][2] * QSC, acc[mi][ni][3] * QSC);
            } else if (z == 1) {
                *(__half2*)&g_kh[(bh * NT + t0) * NDK + d] =
                    __floats2half2_rn(acc[mi][ni][0], acc[mi][ni][1]);
                *(__half2*)&g_kh[(bh * NT + t0 + 8) * NDK + d] =
                    __floats2half2_rn(acc[mi][ni][2], acc[mi][ni][3]);
            } else {
                g_vt[(bh * NDK + d    ) * NT + t0    ] = __float2half_rn(acc[mi][ni][0]);
                g_vt[(bh * NDK + d + 1) * NT + t0    ] = __float2half_rn(acc[mi][ni][1]);
                g_vt[(bh * NDK + d    ) * NT + t0 + 8] = __float2half_rn(acc[mi][ni][2]);
                g_vt[(bh * NDK + d + 1) * NT + t0 + 8] = __float2half_rn(acc[mi][ni][3]);
            }
        }
    }
}

// ---------------------------------------------------------------------------
// Flash attention v2: fp16 mma + ldmatrix K/V + register-resident P + exp2.
// Scores are already in log2 domain (Q pre-scaled by 0.125*log2e).
// ---------------------------------------------------------------------------
#define AT_STRIDE 72
#define AT_KOFF   (128 * AT_STRIDE)
#define AT_VOFF   (AT_KOFF + 2 * 64 * AT_STRIDE)
#define AT_SMEM   ((AT_VOFF + 2 * 64 * AT_STRIDE) * 2)

__global__ __launch_bounds__(256, 2) void attn_h(float* __restrict__ out)
{
    extern __shared__ __half smh[];
    const uint32_t smb = smem_u32(smh);

    const int qt = 15 - (int)blockIdx.x;
    const int bh = blockIdx.y;
    const int b  = bh >> 4;
    const int h  = bh & 15;
    const int q0 = qt * 128;

    const __half* qg = g_qh + (size_t)bh * NT * NDK;
    const __half* kg = g_kh + (size_t)bh * NT * NDK;
    const __half* vg = g_vt + (size_t)bh * NDK * NT;

    const int tid  = threadIdx.x;
    const int wid  = tid >> 5;
    const int lane = tid & 31;
    const int qr   = lane >> 2;
    const int qc   = lane & 3;

    const int row_ = tid >> 3;
    const int ch_  = (tid & 7) * 8;

    // ldmatrix per-lane byte offset within an n-major/k-contig tile:
    // lane -> row (lane&7), k-chunk (lane>>3)*8 halves
    const uint32_t lmoff = (uint32_t)(((lane & 7) * AT_STRIDE + (lane >> 3) * 8) * 2);

    // Q tile (group A)
    #pragma unroll
    for (int j = 0; j < 4; j++) {
        int row = row_ + j * 32;
        CP_ASYNC16(smb + (uint32_t)(row * AT_STRIDE + ch_) * 2,
                   qg + (size_t)(q0 + row) * NDK + ch_);
    }
    CP_COMMIT;

    // K/V tile 0 (group B)
    #pragma unroll
    for (int j = 0; j < 2; j++) {
        int row = row_ + j * 32;
        CP_ASYNC16(smb + (uint32_t)(AT_KOFF + row * AT_STRIDE + ch_) * 2,
                   kg + (size_t)row * NDK + ch_);
        CP_ASYNC16(smb + (uint32_t)(AT_VOFF + row * AT_STRIDE + ch_) * 2,
                   vg + (size_t)row * NT + ch_);
    }
    CP_COMMIT;

    CP_WAIT(1);
    __syncthreads();

    // Q fragments (already scaled by 0.125*log2e)
    uint32_t qf[4][4];
    {
        const __half* Qw = smh + (wid * 16) * AT_STRIDE;
        #pragma unroll
        for (int ks = 0; ks < 4; ks++) {
            const __half* p = Qw + qr * AT_STRIDE + ks * 16 + 2 * qc;
            qf[ks][0] = *(const uint32_t*)(p);
            qf[ks][1] = *(const uint32_t*)(p + 8 * AT_STRIDE);
            qf[ks][2] = *(const uint32_t*)(p + 8);
            qf[ks][3] = *(const uint32_t*)(p + 8 * AT_STRIDE + 8);
        }
    }

    float o[8][4];
    #pragma unroll
    for (int ni = 0; ni < 8; ni++)
        #pragma unroll
        for (int v = 0; v < 4; v++) o[ni][v] = 0.0f;
    float m0 = -INFINITY, m1 = -INFINITY, l0 = 0.0f, l1 = 0.0f;

    const int ntiles = 2 * qt + 2;

    for (int kt = 0; kt < ntiles; kt++) {
        if (kt + 1 < ntiles) {
            const int s1 = (kt + 1) * 64;
            const uint32_t kb = AT_KOFF + ((kt + 1) & 1) * 64 * AT_STRIDE;
            const uint32_t vb = AT_VOFF + ((kt + 1) & 1) * 64 * AT_STRIDE;
            #pragma unroll
            for (int j = 0; j < 2; j++) {
                int row = row_ + j * 32;
                CP_ASYNC16(smb + (kb + row * AT_STRIDE + ch_) * 2,
                           kg + (size_t)(s1 + row) * NDK + ch_);
                CP_ASYNC16(smb + (vb + row * AT_STRIDE + ch_) * 2,
                           vg + (size_t)row * NT + s1 + ch_);
            }
            CP_COMMIT;
            CP_WAIT(1);
        } else {
            CP_WAIT(0);
        }
        __syncthreads();

        const uint32_t Kb = smb + (AT_KOFF + (kt & 1) * 64 * AT_STRIDE) * 2 + lmoff;
        const uint32_t Vb = smb + (AT_VOFF + (kt & 1) * 64 * AT_STRIDE) * 2 + lmoff;
        const int s0 = kt * 64;

        // ---- S (log2-scaled) = Q' K^T via ldmatrix B fragments ----
        float sc[8][4];
        #pragma unroll
        for (int ni = 0; ni < 8; ni++)
            #pragma unroll
            for (int v = 0; v < 4; v++) sc[ni][v] = 0.0f;

        #pragma unroll
        for (int ni = 0; ni < 8; ni++) {
            const uint32_t base = Kb + (uint32_t)(ni * 8 * AT_STRIDE * 2);
            uint32_t kf[4];
            ldsm_x4(kf, base);                 // k-chunks 0..31
            mma_f16(sc[ni], qf[0], kf);
            mma_f16(sc[ni], qf[1], kf + 2);
            ldsm_x4(kf, base + 64);            // k-chunks 32..63 (32 halves)
            mma_f16(sc[ni], qf[2], kf);
            mma_f16(sc[ni], qf[3], kf + 2);
        }

        // ---- causal mask (diagonal-overlap tiles only) ----
        if (kt >= 2 * qt) {
            const int r0g = q0 + wid * 16 + qr;
            const int r1g = r0g + 8;
            #pragma unroll
            for (int ni = 0; ni < 8; ni++) {
                const int c = s0 + ni * 8 + 2 * qc;
                if (c     > r0g) sc[ni][0] = -INFINITY;
                if (c + 1 > r0g) sc[ni][1] = -INFINITY;
                if (c     > r1g) sc[ni][2] = -INFINITY;
                if (c + 1 > r1g) sc[ni][3] = -INFINITY;
            }
        }

        // ---- online softmax in base-2 domain ----
        float rmax0 = sc[0][0], rmax1 = sc[0][2];
        #pragma unroll
        for (int ni = 0; ni < 8; ni++) {
            rmax0 = fmaxf(rmax0, fmaxf(sc[ni][0], sc[ni][1]));
            rmax1 = fmaxf(rmax1, fmaxf(sc[ni][2], sc[ni][3]));
        }
        rmax0 = fmaxf(rmax0, __shfl_xor_sync(0xffffffffu, rmax0, 1));
        rmax0 = fmaxf(rmax0, __shfl_xor_sync(0xffffffffu, rmax0, 2));
        rmax1 = fmaxf(rmax1, __shfl_xor_sync(0xffffffffu, rmax1, 1));
        rmax1 = fmaxf(rmax1, __shfl_xor_sync(0xffffffffu, rmax1, 2));

        const float mn0 = fmaxf(m0, rmax0);
        const float mn1 = fmaxf(m1, rmax1);
        const float a0  = exp2f(m0 - mn0);
        const float a1  = exp2f(m1 - mn1);

        float rs0 = 0.0f, rs1 = 0.0f;
        #pragma unroll
        for (int ni = 0; ni < 8; ni++) {
            sc[ni][0] = exp2f(sc[ni][0] - mn0);
            sc[ni][1] = exp2f(sc[ni][1] - mn0);
            sc[ni][2] = exp2f(sc[ni][2] - mn1);
            sc[ni][3] = exp2f(sc[ni][3] - mn1);
            rs0 += sc[ni][0] + sc[ni][1];
            rs1 += sc[ni][2] + sc[ni][3];
        }
        rs0 += __shfl_xor_sync(0xffffffffu, rs0, 1);
        rs0 += __shfl_xor_sync(0xffffffffu, rs0, 2);
        rs1 += __shfl_xor_sync(0xffffffffu, rs1, 1);
        rs1 += __shfl_xor_sync(0xffffffffu, rs1, 2);

        l0 = l0 * a0 + rs0;  m0 = mn0;
        l1 = l1 * a1 + rs1;  m1 = mn1;
        #pragma unroll
        for (int ni = 0; ni < 8; ni++) {
            o[ni][0] *= a0; o[ni][1] *= a0;
            o[ni][2] *= a1; o[ni][3] *= a1;
        }

        // ---- P stays in registers: S C-fragment == PV A-fragment ----
        uint32_t pf[4][4];
        #pragma unroll
        for (int ks = 0; ks < 4; ks++) {
            pf[ks][0] = pack_h2(sc[2*ks    ][0], sc[2*ks    ][1]);
            pf[ks][1] = pack_h2(sc[2*ks    ][2], sc[2*ks    ][3]);
            pf[ks][2] = pack_h2(sc[2*ks + 1][0], sc[2*ks + 1][1]);
            pf[ks][3] = pack_h2(sc[2*ks + 1][2], sc[2*ks + 1][3]);
        }

        // ---- O += P V  (V^T tile [d][s], s-contig, via ldmatrix) ----
        #pragma unroll
        for (int ni = 0; ni < 8; ni++) {
            const uint32_t base = Vb + (uint32_t)(ni * 8 * AT_STRIDE * 2);
            uint32_t vf[4];
            ldsm_x4(vf, base);
            mma_f16(o[ni], pf[0], vf);
            mma_f16(o[ni], pf[1], vf + 2);
            ldsm_x4(vf, base + 64);
            mma_f16(o[ni], pf[2], vf);
            mma_f16(o[ni], pf[3], vf + 2);
        }

        __syncthreads();
    }

    // ---- finalize + write out[b, t, h*64 + v] ----
    const float inv0 = 1.0f / l0;
    const float inv1 = 1.0f / l1;
    const int t0 = q0 + wid * 16 + qr;
    size_t base0 = ((size_t)b * NT + t0) * (NH * NDK) + h * NDK;
    size_t base1 = base0 + 8 * (size_t)(NH * NDK);
    #pragma unroll
    for (int ni = 0; ni < 8; ni++) {
        const int n = ni * 8 + 2 * qc;
        *(float2*)&out[base0 + n] = make_float2(o[ni][0] * inv0, o[ni][1] * inv0);
        *(float2*)&out[base1 + n] = make_float2(o[ni][2] * inv1, o[ni][3] * inv1);
    }
}

// ---------------------------------------------------------------------------
extern "C" void kernel_launch(void* const* d_in, const int* in_sizes, int n_in,
                              void* d_out, int out_size)
{
    (void)in_sizes; (void)n_in; (void)out_size;
    const float* x  = (const float*)d_in[0];
    const float* Wq = (const float*)d_in[1];
    const float* Wk = (const float*)d_in[2];
    const float* Wv = (const float*)d_in[3];
    float* out = (float*)d_out;

    cudaFuncSetAttribute(proj_h,
                         cudaFuncAttributeMaxDynamicSharedMemorySize, PJ_SMEM);
    cudaFuncSetAttribute(attn_h,
                         cudaFuncAttributeMaxDynamicSharedMemorySize, AT_SMEM);

    convert_x<<<NB * NT * NDM / 1024, 256>>>(x);
    convert_w<<<dim3(NDM / 32, NDK / 32, 48), dim3(32, 8)>>>(Wq, Wk, Wv);

    proj_h<<<dim3(NB * NT / 128, 24), 256, PJ_SMEM>>>();

    attn_h<<<dim3(NT / 128, NB * NH), 256, AT_SMEM>>>(out);
}

// round 10
// speedup vs baseline: 6.4916x; 1.0391x over previous
#include <cuda_runtime.h>
#include <cuda_fp16.h>
#include <math.h>
#include <stdint.h>

#define NB 4
#define NT 2048
#define NDM 1024
#define NH 16
#define NDK 64

// fp16 staging buffers
__device__ __half g_xh[NB*NT*NDM];        // x in fp16            [b*t][d]
__device__ __half g_wth[3*NH*NDK*NDM];    // W fp16 transposed    [z*1024+n][d]
__device__ __half g_qh[NB*NH*NT*NDK];     // Q*0.125*log2e fp16   [bh][t][d]
__device__ __half g_kh[NB*NH*NT*NDK];     // K fp16               [bh][t][d]
__device__ __half g_vt[NB*NH*NDK*NT];     // V fp16 TRANSPOSED    [bh][d][t]

__device__ __forceinline__ void mma_f16(float* c, const uint32_t* a, const uint32_t* b) {
    asm volatile("mma.sync.aligned.m16n8k16.row.col.f32.f16.f16.f32 "
                 "{%0,%1,%2,%3}, {%4,%5,%6,%7}, {%8,%9}, {%0,%1,%2,%3};"
                 : "+f"(c[0]), "+f"(c[1]), "+f"(c[2]), "+f"(c[3])
                 : "r"(a[0]), "r"(a[1]), "r"(a[2]), "r"(a[3]),
                   "r"(b[0]), "r"(b[1]));
}
__device__ __forceinline__ void ldsm_x4(uint32_t* d, uint32_t addr) {
    asm volatile("ldmatrix.sync.aligned.m8n8.x4.shared.b16 {%0,%1,%2,%3}, [%4];"
                 : "=r"(d[0]), "=r"(d[1]), "=r"(d[2]), "=r"(d[3]) : "r"(addr));
}
__device__ __forceinline__ uint32_t smem_u32(const void* p) {
    uint32_t a;
    asm("{ .reg .u64 t; cvta.to.shared.u64 t, %1; cvt.u32.u64 %0, t; }"
        : "=r"(a) : "l"(p));
    return a;
}
__device__ __forceinline__ uint32_t pack_h2(float lo, float hi) {
    __half2 h = __floats2half2_rn(lo, hi);
    return *(uint32_t*)&h;
}
#define CP_ASYNC16(dst, src) \
    asm volatile("cp.async.cg.shared.global [%0], [%1], 16;" \
                 :: "r"(dst), "l"(src) : "memory")
#define CP_COMMIT  asm volatile("cp.async.commit_group;" ::: "memory")
#define CP_WAIT(n) asm volatile("cp.async.wait_group %0;" :: "n"(n) : "memory")

// ---------------------------------------------------------------------------
// Pre-pass 1: x -> fp16
// ---------------------------------------------------------------------------
__global__ __launch_bounds__(256) void convert_x(const float* __restrict__ x)
{
    const int i = ((int)blockIdx.x * 256 + (int)threadIdx.x) * 4;
    float4 v = *(const float4*)&x[i];
    *(__half2*)&g_xh[i]     = __floats2half2_rn(v.x, v.y);
    *(__half2*)&g_xh[i + 2] = __floats2half2_rn(v.z, v.w);
}

// ---------------------------------------------------------------------------
// Pre-pass 2: W[h][d][n] -> Wt fp16 [z*1024 + h*64 + n][d]
// ---------------------------------------------------------------------------
__global__ __launch_bounds__(256) void convert_w(
    const float* __restrict__ Wq, const float* __restrict__ Wk,
    const float* __restrict__ Wv)
{
    __shared__ float tile[32][33];
    const int zh = blockIdx.z;
    const int z = zh >> 4, h = zh & 15;
    const float* W = (z == 0 ? Wq : z == 1 ? Wk : Wv) + (size_t)h * NDM * NDK;
    const int d0 = blockIdx.x * 32;
    const int n0 = blockIdx.y * 32;
    const int tx = threadIdx.x, ty = threadIdx.y;

    #pragma unroll
    for (int j = 0; j < 4; j++)
        tile[ty + j * 8][tx] = W[(size_t)(d0 + ty + j * 8) * NDK + n0 + tx];
    __syncthreads();
    __half* dst = g_wth + ((size_t)(z * NH + h) * NDK) * NDM;
    #pragma unroll
    for (int j = 0; j < 4; j++)
        dst[(size_t)(n0 + ty + j * 8) * NDM + d0 + tx] =
            __float2half_rn(tile[tx][ty + j * 8]);
}

// ---------------------------------------------------------------------------
// Projection GEMM on fp16 m16n8k16 + ldmatrix fragments.
// CTA: M=128 x N=128 x K=1024, BK=64, cp.async double buffer, 8 warps (4x2),
// warp tile 32x64. 24 ldmatrix.x4 + 64 mma per warp per stage.
// V output is staged through smem as [d][t] then stored coalesced.
// ---------------------------------------------------------------------------
#define PJ_STRIDE 72
#define PJ_TILE   (128 * PJ_STRIDE)
#define PJ_STAGE  (2 * PJ_TILE)
#define PJ_SMEM   (2 * PJ_STAGE * 2)     // 73728 B
#define VST 136                          // V staging stride (halves)

__global__ __launch_bounds__(256, 2) void proj_h()
{
    extern __shared__ __half smh[];
    const uint32_t smb = smem_u32(smh);

    const int m0 = blockIdx.x * 128;
    const int by = blockIdx.y;
    const int z  = by >> 3;
    const int n0 = (by & 7) * 128;
    const __half* wt = g_wth + (size_t)(z * 1024 + n0) * NDM;

    const int tid  = threadIdx.x;
    const int wid  = tid >> 5;
    const int lane = tid & 31;
    const int qr   = lane >> 2;
    const int qc   = lane & 3;
    const int wr   = wid >> 1;
    const int wc   = wid & 1;

    const int row_ = tid >> 3;
    const int ch_  = (tid & 7) * 8;

    // ldmatrix per-lane byte offsets (stage-invariant parts)
    const uint32_t aoff = (uint32_t)(((wr * 32 + (lane & 15)) * PJ_STRIDE
                                      + (lane >> 4) * 8) * 2);
    const uint32_t boff = (uint32_t)(((wc * 64 + (lane & 7)) * PJ_STRIDE
                                      + (lane >> 3) * 8) * 2);

    float acc[2][8][4];
    #pragma unroll
    for (int mi = 0; mi < 2; mi++)
        #pragma unroll
        for (int ni = 0; ni < 8; ni++)
            #pragma unroll
            for (int v = 0; v < 4; v++) acc[mi][ni][v] = 0.0f;

    #pragma unroll
    for (int j = 0; j < 4; j++) {
        int row = row_ + j * 32;
        CP_ASYNC16(smb + (uint32_t)(row * PJ_STRIDE + ch_) * 2,
                   g_xh + (size_t)(m0 + row) * NDM + ch_);
        CP_ASYNC16(smb + (uint32_t)(PJ_TILE + row * PJ_STRIDE + ch_) * 2,
                   wt + (size_t)row * NDM + ch_);
    }
    CP_COMMIT;

    for (int s = 0; s < 16; s++) {
        if (s + 1 < 16) {
            const int k1 = (s + 1) * 64;
            const uint32_t sb = (uint32_t)(((s + 1) & 1) * PJ_STAGE);
            #pragma unroll
            for (int j = 0; j < 4; j++) {
                int row = row_ + j * 32;
                CP_ASYNC16(smb + (sb + row * PJ_STRIDE + ch_) * 2,
                           g_xh + (size_t)(m0 + row) * NDM + k1 + ch_);
                CP_ASYNC16(smb + (sb + PJ_TILE + row * PJ_STRIDE + ch_) * 2,
                           wt + (size_t)row * NDM + k1 + ch_);
            }
            CP_COMMIT;
            CP_WAIT(1);
        } else {
            CP_WAIT(0);
        }
        __syncthreads();

        const uint32_t Ab = smb + (uint32_t)((s & 1) * PJ_STAGE) * 2 + aoff;
        const uint32_t Bb = smb + (uint32_t)((s & 1) * PJ_STAGE + PJ_TILE) * 2 + boff;

        #pragma unroll
        for (int ks2 = 0; ks2 < 2; ks2++) {
            uint32_t bfr[8][4];
            #pragma unroll
            for (int ni = 0; ni < 8; ni++)
                ldsm_x4(bfr[ni], Bb + (uint32_t)(ni * 8 * PJ_STRIDE * 2 + ks2 * 64));
            #pragma unroll
            for (int ks = 0; ks < 2; ks++) {
                uint32_t af[2][4];
                const uint32_t ka = (uint32_t)((ks2 * 2 + ks) * 32);
                ldsm_x4(af[0], Ab + ka);
                ldsm_x4(af[1], Ab + (uint32_t)(16 * PJ_STRIDE * 2) + ka);
                #pragma unroll
                for (int mi = 0; mi < 2; mi++)
                    #pragma unroll
                    for (int ni = 0; ni < 8; ni++)
                        mma_f16(acc[mi][ni], af[mi], bfr[ni] + 2 * ks);
            }
        }
        __syncthreads();
    }

    const float QSC = 0.125f * 1.44269504088896340736f;   // 1/8 * log2(e)
    const int b     = m0 >> 11;
    const int tbase = m0 & 2047;

    if (z < 2) {
        // Q / K: direct coalesced half2 stores
        #pragma unroll
        for (int mi = 0; mi < 2; mi++) {
            const int t0 = tbase + wr * 32 + mi * 16 + qr;
            #pragma unroll
            for (int ni = 0; ni < 8; ni++) {
                const int ncta = wc * 64 + ni * 8 + 2 * qc;
                const int ng   = n0 + ncta;
                const int h    = ng >> 6;
                const int d    = ng & 63;
                const size_t bh = (size_t)(b * NH + h);
                if (z == 0) {
                    *(__half2*)&g_qh[(bh * NT + t0) * NDK + d] =
                        __floats2half2_rn(acc[mi][ni][0] * QSC, acc[mi][ni][1] * QSC);
                    *(__half2*)&g_qh[(bh * NT + t0 + 8) * NDK + d] =
                        __floats2half2_rn(acc[mi][ni][2] * QSC, acc[mi][ni][3] * QSC);
                } else {
                    *(__half2*)&g_kh[(bh * NT + t0) * NDK + d] =
                        __floats2half2_rn(acc[mi][ni][0], acc[mi][ni][1]);
                    *(__half2*)&g_kh[(bh * NT + t0 + 8) * NDK + d] =
                        __floats2half2_rn(acc[mi][ni][2], acc[mi][ni][3]);
                }
            }
        }
    } else {
        // V: stage transposed [d_local][t_local] tile in smem, then coalesced copy
        #pragma unroll
        for (int mi = 0; mi < 2; mi++) {
            const int tl = wr * 32 + mi * 16 + qr;      // 0..127
            #pragma unroll
            for (int ni = 0; ni < 8; ni++) {
                const int dl = wc * 64 + ni * 8 + 2 * qc;
                smh[(dl    ) * VST + tl    ] = __float2half_rn(acc[mi][ni][0]);
                smh[(dl + 1) * VST + tl    ] = __float2half_rn(acc[mi][ni][1]);
                smh[(dl    ) * VST + tl + 8] = __float2half_rn(acc[mi][ni][2]);
                smh[(dl + 1) * VST + tl + 8] = __float2half_rn(acc[mi][ni][3]);
            }
        }
        __syncthreads();
        const int cr = tid >> 4;          // base d row
        const int cc = (tid & 15) * 8;    // half offset within t row
        #pragma unroll
        for (int j = 0; j < 8; j++) {
            const int r  = cr + j * 16;   // d_local 0..127
            const int ng = n0 + r;
            const int h  = ng >> 6;
            const int d  = ng & 63;
            __half* dst = g_vt + ((size_t)(b * NH + h) * NDK + d) * NT + tbase + cc;
            *(float4*)dst = *(const float4*)&smh[r * VST + cc];
        }
    }
}

// ---------------------------------------------------------------------------
// Flash attention (unchanged from round 9): fp16 mma + ldmatrix + reg-P + exp2.
// ---------------------------------------------------------------------------
#define AT_STRIDE 72
#define AT_KOFF   (128 * AT_STRIDE)
#define AT_VOFF   (AT_KOFF + 2 * 64 * AT_STRIDE)
#define AT_SMEM   ((AT_VOFF + 2 * 64 * AT_STRIDE) * 2)

__global__ __launch_bounds__(256, 2) void attn_h(float* __restrict__ out)
{
    extern __shared__ __half smh[];
    const uint32_t smb = smem_u32(smh);

    const int qt = 15 - (int)blockIdx.x;
    const int bh = blockIdx.y;
    const int b  = bh >> 4;
    const int h  = bh & 15;
    const int q0 = qt * 128;

    const __half* qg = g_qh + (size_t)bh * NT * NDK;
    const __half* kg = g_kh + (size_t)bh * NT * NDK;
    const __half* vg = g_vt + (size_t)bh * NDK * NT;

    const int tid  = threadIdx.x;
    const int wid  = tid >> 5;
    const int lane = tid & 31;
    const int qr   = lane >> 2;
    const int qc   = lane & 3;

    const int row_ = tid >> 3;
    const int ch_  = (tid & 7) * 8;

    const uint32_t lmoff = (uint32_t)(((lane & 7) * AT_STRIDE + (lane >> 3) * 8) * 2);

    #pragma unroll
    for (int j = 0; j < 4; j++) {
        int row = row_ + j * 32;
        CP_ASYNC16(smb + (uint32_t)(row * AT_STRIDE + ch_) * 2,
                   qg + (size_t)(q0 + row) * NDK + ch_);
    }
    CP_COMMIT;

    #pragma unroll
    for (int j = 0; j < 2; j++) {
        int row = row_ + j * 32;
        CP_ASYNC16(smb + (uint32_t)(AT_KOFF + row * AT_STRIDE + ch_) * 2,
                   kg + (size_t)row * NDK + ch_);
        CP_ASYNC16(smb + (uint32_t)(AT_VOFF + row * AT_STRIDE + ch_) * 2,
                   vg + (size_t)row * NT + ch_);
    }
    CP_COMMIT;

    CP_WAIT(1);
    __syncthreads();

    uint32_t qf[4][4];
    {
        const __half* Qw = smh + (wid * 16) * AT_STRIDE;
        #pragma unroll
        for (int ks = 0; ks < 4; ks++) {
            const __half* p = Qw + qr * AT_STRIDE + ks * 16 + 2 * qc;
            qf[ks][0] = *(const uint32_t*)(p);
            qf[ks][1] = *(const uint32_t*)(p + 8 * AT_STRIDE);
            qf[ks][2] = *(const uint32_t*)(p + 8);
            qf[ks][3] = *(const uint32_t*)(p + 8 * AT_STRIDE + 8);
        }
    }

    float o[8][4];
    #pragma unroll
    for (int ni = 0; ni < 8; ni++)
        #pragma unroll
        for (int v = 0; v < 4; v++) o[ni][v] = 0.0f;
    float m0 = -INFINITY, m1 = -INFINITY, l0 = 0.0f, l1 = 0.0f;

    const int ntiles = 2 * qt + 2;

    for (int kt = 0; kt < ntiles; kt++) {
        if (kt + 1 < ntiles) {
            const int s1 = (kt + 1) * 64;
            const uint32_t kb = AT_KOFF + ((kt + 1) & 1) * 64 * AT_STRIDE;
            const uint32_t vb = AT_VOFF + ((kt + 1) & 1) * 64 * AT_STRIDE;
            #pragma unroll
            for (int j = 0; j < 2; j++) {
                int row = row_ + j * 32;
                CP_ASYNC16(smb + (kb + row * AT_STRIDE + ch_) * 2,
                           kg + (size_t)(s1 + row) * NDK + ch_);
                CP_ASYNC16(smb + (vb + row * AT_STRIDE + ch_) * 2,
                           vg + (size_t)row * NT + s1 + ch_);
            }
            CP_COMMIT;
            CP_WAIT(1);
        } else {
            CP_WAIT(0);
        }
        __syncthreads();

        const uint32_t Kb = smb + (AT_KOFF + (kt & 1) * 64 * AT_STRIDE) * 2 + lmoff;
        const uint32_t Vb = smb + (AT_VOFF + (kt & 1) * 64 * AT_STRIDE) * 2 + lmoff;
        const int s0 = kt * 64;

        float sc[8][4];
        #pragma unroll
        for (int ni = 0; ni < 8; ni++)
            #pragma unroll
            for (int v = 0; v < 4; v++) sc[ni][v] = 0.0f;

        #pragma unroll
        for (int ni = 0; ni < 8; ni++) {
            const uint32_t base = Kb + (uint32_t)(ni * 8 * AT_STRIDE * 2);
            uint32_t kf[4];
            ldsm_x4(kf, base);
            mma_f16(sc[ni], qf[0], kf);
            mma_f16(sc[ni], qf[1], kf + 2);
            ldsm_x4(kf, base + 64);
            mma_f16(sc[ni], qf[2], kf);
            mma_f16(sc[ni], qf[3], kf + 2);
        }

        if (kt >= 2 * qt) {
            const int r0g = q0 + wid * 16 + qr;
            const int r1g = r0g + 8;
            #pragma unroll
            for (int ni = 0; ni < 8; ni++) {
                const int c = s0 + ni * 8 + 2 * qc;
                if (c     > r0g) sc[ni][0] = -INFINITY;
                if (c + 1 > r0g) sc[ni][1] = -INFINITY;
                if (c     > r1g) sc[ni][2] = -INFINITY;
                if (c + 1 > r1g) sc[ni][3] = -INFINITY;
            }
        }

        float rmax0 = sc[0][0], rmax1 = sc[0][2];
        #pragma unroll
        for (int ni = 0; ni < 8; ni++) {
            rmax0 = fmaxf(rmax0, fmaxf(sc[ni][0], sc[ni][1]));
            rmax1 = fmaxf(rmax1, fmaxf(sc[ni][2], sc[ni][3]));
        }
        rmax0 = fmaxf(rmax0, __shfl_xor_sync(0xffffffffu, rmax0, 1));
        rmax0 = fmaxf(rmax0, __shfl_xor_sync(0xffffffffu, rmax0, 2));
        rmax1 = fmaxf(rmax1, __shfl_xor_sync(0xffffffffu, rmax1, 1));
        rmax1 = fmaxf(rmax1, __shfl_xor_sync(0xffffffffu, rmax1, 2));

        const float mn0 = fmaxf(m0, rmax0);
        const float mn1 = fmaxf(m1, rmax1);
        const float a0  = exp2f(m0 - mn0);
        const float a1  = exp2f(m1 - mn1);

        float rs0 = 0.0f, rs1 = 0.0f;
        #pragma unroll
        for (int ni = 0; ni < 8; ni++) {
            sc[ni][0] = exp2f(sc[ni][0] - mn0);
            sc[ni][1] = exp2f(sc[ni][1] - mn0);
            sc[ni][2] = exp2f(sc[ni][2] - mn1);
            sc[ni][3] = exp2f(sc[ni][3] - mn1);
            rs0 += sc[ni][0] + sc[ni][1];
            rs1 += sc[ni][2] + sc[ni][3];
        }
        rs0 += __shfl_xor_sync(0xffffffffu, rs0, 1);
        rs0 += __shfl_xor_sync(0xffffffffu, rs0, 2);
        rs1 += __shfl_xor_sync(0xffffffffu, rs1, 1);
        rs1 += __shfl_xor_sync(0xffffffffu, rs1, 2);

        l0 = l0 * a0 + rs0;  m0 = mn0;
        l1 = l1 * a1 + rs1;  m1 = mn1;
        #pragma unroll
        for (int ni = 0; ni < 8; ni++) {
            o[ni][0] *= a0; o[ni][1] *= a0;
            o[ni][2] *= a1; o[ni][3] *= a1;
        }

        uint32_t pf[4][4];
        #pragma unroll
        for (int ks = 0; ks < 4; ks++) {
            pf[ks][0] = pack_h2(sc[2*ks    ][0], sc[2*ks    ][1]);
            pf[ks][1] = pack_h2(sc[2*ks    ][2], sc[2*ks    ][3]);
            pf[ks][2] = pack_h2(sc[2*ks + 1][0], sc[2*ks + 1][1]);
            pf[ks][3] = pack_h2(sc[2*ks + 1][2], sc[2*ks + 1][3]);
        }

        #pragma unroll
        for (int ni = 0; ni < 8; ni++) {
            const uint32_t base = Vb + (uint32_t)(ni * 8 * AT_STRIDE * 2);
            uint32_t vf[4];
            ldsm_x4(vf, base);
            mma_f16(o[ni], pf[0], vf);
            mma_f16(o[ni], pf[1], vf + 2);
            ldsm_x4(vf, base + 64);
            mma_f16(o[ni], pf[2], vf);
            mma_f16(o[ni], pf[3], vf + 2);
        }

        __syncthreads();
    }

    const float inv0 = 1.0f / l0;
    const float inv1 = 1.0f / l1;
    const int t0 = q0 + wid * 16 + qr;
    size_t base0 = ((size_t)b * NT + t0) * (NH * NDK) + h * NDK;
    size_t base1 = base0 + 8 * (size_t)(NH * NDK);
    #pragma unroll
    for (int ni = 0; ni < 8; ni++) {
        const int n = ni * 8 + 2 * qc;
        *(float2*)&out[base0 + n] = make_float2(o[ni][0] * inv0, o[ni][1] * inv0);
        *(float2*)&out[base1 + n] = make_float2(o[ni][2] * inv1, o[ni][3] * inv1);
    }
}

// ---------------------------------------------------------------------------
extern "C" void kernel_launch(void* const* d_in, const int* in_sizes, int n_in,
                              void* d_out, int out_size)
{
    (void)in_sizes; (void)n_in; (void)out_size;
    const float* x  = (const float*)d_in[0];
    const float* Wq = (const float*)d_in[1];
    const float* Wk = (const float*)d_in[2];
    const float* Wv = (const float*)d_in[3];
    float* out = (float*)d_out;

    cudaFuncSetAttribute(proj_h,
                         cudaFuncAttributeMaxDynamicSharedMemorySize, PJ_SMEM);
    cudaFuncSetAttribute(attn_h,
                         cudaFuncAttributeMaxDynamicSharedMemorySize, AT_SMEM);

    convert_x<<<NB * NT * NDM / 1024, 256>>>(x);
    convert_w<<<dim3(NDM / 32, NDK / 32, 48), dim3(32, 8)>>>(Wq, Wk, Wv);

    proj_h<<<dim3(NB * NT / 128, 24), 256, PJ_SMEM>>>();

    attn_h<<<dim3(NT / 128, NB * NH), 256, AT_SMEM>>>(out);
}

// round 11
// speedup vs baseline: 6.6805x; 1.0291x over previous
#include <cuda_runtime.h>
#include <cuda_fp16.h>
#include <math.h>
#include <stdint.h>

#define NB 4
#define NT 2048
#define NDM 1024
#define NH 16
#define NDK 64

// fp16 staging buffers
__device__ __half g_xh[NB*NT*NDM];        // x in fp16            [b*t][d]
__device__ __half g_wth[3*NH*NDK*NDM];    // W fp16 transposed    [z*1024+n][d]
__device__ __half g_qh[NB*NH*NT*NDK];     // Q*0.125*log2e fp16   [bh][t][d]
__device__ __half g_kh[NB*NH*NT*NDK];     // K fp16               [bh][t][d]
__device__ __half g_vt[NB*NH*NDK*NT];     // V fp16 TRANSPOSED    [bh][d][t]

__device__ __forceinline__ void mma_f16(float* c, const uint32_t* a, const uint32_t* b) {
    asm volatile("mma.sync.aligned.m16n8k16.row.col.f32.f16.f16.f32 "
                 "{%0,%1,%2,%3}, {%4,%5,%6,%7}, {%8,%9}, {%0,%1,%2,%3};"
                 : "+f"(c[0]), "+f"(c[1]), "+f"(c[2]), "+f"(c[3])
                 : "r"(a[0]), "r"(a[1]), "r"(a[2]), "r"(a[3]),
                   "r"(b[0]), "r"(b[1]));
}
__device__ __forceinline__ void ldsm_x4(uint32_t* d, uint32_t addr) {
    asm volatile("ldmatrix.sync.aligned.m8n8.x4.shared.b16 {%0,%1,%2,%3}, [%4];"
                 : "=r"(d[0]), "=r"(d[1]), "=r"(d[2]), "=r"(d[3]) : "r"(addr));
}
__device__ __forceinline__ uint32_t smem_u32(const void* p) {
    uint32_t a;
    asm("{ .reg .u64 t; cvta.to.shared.u64 t, %1; cvt.u32.u64 %0, t; }"
        : "=r"(a) : "l"(p));
    return a;
}
__device__ __forceinline__ uint32_t h2e(float lo, float hi) {
    __half2 h = h2exp2(__floats2half2_rn(lo, hi));
    return *(uint32_t*)&h;
}
#define CP_ASYNC16(dst, src) \
    asm volatile("cp.async.cg.shared.global [%0], [%1], 16;" \
                 :: "r"(dst), "l"(src) : "memory")
#define CP_COMMIT  asm volatile("cp.async.commit_group;" ::: "memory")
#define CP_WAIT(n) asm volatile("cp.async.wait_group %0;" :: "n"(n) : "memory")

// ---------------------------------------------------------------------------
// Pre-pass 1: x -> fp16
// ---------------------------------------------------------------------------
__global__ __launch_bounds__(256) void convert_x(const float* __restrict__ x)
{
    const int i = ((int)blockIdx.x * 256 + (int)threadIdx.x) * 4;
    float4 v = *(const float4*)&x[i];
    *(__half2*)&g_xh[i]     = __floats2half2_rn(v.x, v.y);
    *(__half2*)&g_xh[i + 2] = __floats2half2_rn(v.z, v.w);
}

// ---------------------------------------------------------------------------
// Pre-pass 2: W[h][d][n] -> Wt fp16 [z*1024 + h*64 + n][d]
// ---------------------------------------------------------------------------
__global__ __launch_bounds__(256) void convert_w(
    const float* __restrict__ Wq, const float* __restrict__ Wk,
    const float* __restrict__ Wv)
{
    __shared__ float tile[32][33];
    const int zh = blockIdx.z;
    const int z = zh >> 4, h = zh & 15;
    const float* W = (z == 0 ? Wq : z == 1 ? Wk : Wv) + (size_t)h * NDM * NDK;
    const int d0 = blockIdx.x * 32;
    const int n0 = blockIdx.y * 32;
    const int tx = threadIdx.x, ty = threadIdx.y;

    #pragma unroll
    for (int j = 0; j < 4; j++)
        tile[ty + j * 8][tx] = W[(size_t)(d0 + ty + j * 8) * NDK + n0 + tx];
    __syncthreads();
    __half* dst = g_wth + ((size_t)(z * NH + h) * NDK) * NDM;
    #pragma unroll
    for (int j = 0; j < 4; j++)
        dst[(size_t)(n0 + ty + j * 8) * NDM + d0 + tx] =
            __float2half_rn(tile[tx][ty + j * 8]);
}

// ---------------------------------------------------------------------------
// Projection GEMM on fp16 m16n8k16 + ldmatrix (unchanged from round 10).
// ---------------------------------------------------------------------------
#define PJ_STRIDE 72
#define PJ_TILE   (128 * PJ_STRIDE)
#define PJ_STAGE  (2 * PJ_TILE)
#define PJ_SMEM   (2 * PJ_STAGE * 2)
#define VST 136

__global__ __launch_bounds__(256, 2) void proj_h()
{
    extern __shared__ __half smh[];
    const uint32_t smb = smem_u32(smh);

    const int m0 = blockIdx.x * 128;
    const int by = blockIdx.y;
    const int z  = by >> 3;
    const int n0 = (by & 7) * 128;
    const __half* wt = g_wth + (size_t)(z * 1024 + n0) * NDM;

    const int tid  = threadIdx.x;
    const int lane = tid & 31;
    const int qr   = lane >> 2;
    const int qc   = lane & 3;
    const int wid  = tid >> 5;
    const int wr   = wid >> 1;
    const int wc   = wid & 1;

    const int row_ = tid >> 3;
    const int ch_  = (tid & 7) * 8;

    const uint32_t aoff = (uint32_t)(((wr * 32 + (lane & 15)) * PJ_STRIDE
                                      + (lane >> 4) * 8) * 2);
    const uint32_t boff = (uint32_t)(((wc * 64 + (lane & 7)) * PJ_STRIDE
                                      + (lane >> 3) * 8) * 2);

    float acc[2][8][4];
    #pragma unroll
    for (int mi = 0; mi < 2; mi++)
        #pragma unroll
        for (int ni = 0; ni < 8; ni++)
            #pragma unroll
            for (int v = 0; v < 4; v++) acc[mi][ni][v] = 0.0f;

    #pragma unroll
    for (int j = 0; j < 4; j++) {
        int row = row_ + j * 32;
        CP_ASYNC16(smb + (uint32_t)(row * PJ_STRIDE + ch_) * 2,
                   g_xh + (size_t)(m0 + row) * NDM + ch_);
        CP_ASYNC16(smb + (uint32_t)(PJ_TILE + row * PJ_STRIDE + ch_) * 2,
                   wt + (size_t)row * NDM + ch_);
    }
    CP_COMMIT;

    for (int s = 0; s < 16; s++) {
        if (s + 1 < 16) {
            const int k1 = (s + 1) * 64;
            const uint32_t sb = (uint32_t)(((s + 1) & 1) * PJ_STAGE);
            #pragma unroll
            for (int j = 0; j < 4; j++) {
                int row = row_ + j * 32;
                CP_ASYNC16(smb + (sb + row * PJ_STRIDE + ch_) * 2,
                           g_xh + (size_t)(m0 + row) * NDM + k1 + ch_);
                CP_ASYNC16(smb + (sb + PJ_TILE + row * PJ_STRIDE + ch_) * 2,
                           wt + (size_t)row * NDM + k1 + ch_);
            }
            CP_COMMIT;
            CP_WAIT(1);
        } else {
            CP_WAIT(0);
        }
        __syncthreads();

        const uint32_t Ab = smb + (uint32_t)((s & 1) * PJ_STAGE) * 2 + aoff;
        const uint32_t Bb = smb + (uint32_t)((s & 1) * PJ_STAGE + PJ_TILE) * 2 + boff;

        #pragma unroll
        for (int ks2 = 0; ks2 < 2; ks2++) {
            uint32_t bfr[8][4];
            #pragma unroll
            for (int ni = 0; ni < 8; ni++)
                ldsm_x4(bfr[ni], Bb + (uint32_t)(ni * 8 * PJ_STRIDE * 2 + ks2 * 64));
            #pragma unroll
            for (int ks = 0; ks < 2; ks++) {
                uint32_t af[2][4];
                const uint32_t ka = (uint32_t)((ks2 * 2 + ks) * 32);
                ldsm_x4(af[0], Ab + ka);
                ldsm_x4(af[1], Ab + (uint32_t)(16 * PJ_STRIDE * 2) + ka);
                #pragma unroll
                for (int mi = 0; mi < 2; mi++)
                    #pragma unroll
                    for (int ni = 0; ni < 8; ni++)
                        mma_f16(acc[mi][ni], af[mi], bfr[ni] + 2 * ks);
            }
        }
        __syncthreads();
    }

    const float QSC = 0.125f * 1.44269504088896340736f;
    const int b     = m0 >> 11;
    const int tbase = m0 & 2047;

    if (z < 2) {
        #pragma unroll
        for (int mi = 0; mi < 2; mi++) {
            const int t0 = tbase + wr * 32 + mi * 16 + qr;
            #pragma unroll
            for (int ni = 0; ni < 8; ni++) {
                const int ncta = wc * 64 + ni * 8 + 2 * qc;
                const int ng   = n0 + ncta;
                const int h    = ng >> 6;
                const int d    = ng & 63;
                const size_t bh = (size_t)(b * NH + h);
                if (z == 0) {
                    *(__half2*)&g_qh[(bh * NT + t0) * NDK + d] =
                        __floats2half2_rn(acc[mi][ni][0] * QSC, acc[mi][ni][1] * QSC);
                    *(__half2*)&g_qh[(bh * NT + t0 + 8) * NDK + d] =
                        __floats2half2_rn(acc[mi][ni][2] * QSC, acc[mi][ni][3] * QSC);
                } else {
                    *(__half2*)&g_kh[(bh * NT + t0) * NDK + d] =
                        __floats2half2_rn(acc[mi][ni][0], acc[mi][ni][1]);
                    *(__half2*)&g_kh[(bh * NT + t0 + 8) * NDK + d] =
                        __floats2half2_rn(acc[mi][ni][2], acc[mi][ni][3]);
                }
            }
        }
    } else {
        #pragma unroll
        for (int mi = 0; mi < 2; mi++) {
            const int tl = wr * 32 + mi * 16 + qr;
            #pragma unroll
            for (int ni = 0; ni < 8; ni++) {
                const int dl = wc * 64 + ni * 8 + 2 * qc;
                smh[(dl    ) * VST + tl    ] = __float2half_rn(acc[mi][ni][0]);
                smh[(dl + 1) * VST + tl    ] = __float2half_rn(acc[mi][ni][1]);
                smh[(dl    ) * VST + tl + 8] = __float2half_rn(acc[mi][ni][2]);
                smh[(dl + 1) * VST + tl + 8] = __float2half_rn(acc[mi][ni][3]);
            }
        }
        __syncthreads();
        const int cr = tid >> 4;
        const int cc = (tid & 15) * 8;
        #pragma unroll
        for (int j = 0; j < 8; j++) {
            const int r  = cr + j * 16;
            const int ng = n0 + r;
            const int h  = ng >> 6;
            const int d  = ng & 63;
            __half* dst = g_vt + ((size_t)(b * NH + h) * NDK + d) * NT + tbase + cc;
            *(float4*)dst = *(const float4*)&smh[r * VST + cc];
        }
    }
}

// ---------------------------------------------------------------------------
// Flash attention v3: triple-buffered K/V (one barrier/tile), row sums via
// ones-column mma (no shuffle reductions for l), f16x2 exp2 for P.
// Smem halves: Q 128x72 | K 3x64x72 | V 3x64x72 = 36864 (73728 B).
// ---------------------------------------------------------------------------
#define AT_STRIDE 72
#define AT_TILEH  (64 * AT_STRIDE)            // 4608 halves per K/V tile
#define AT_KOFF   (128 * AT_STRIDE)           // 9216
#define AT_VOFF   (AT_KOFF + 3 * AT_TILEH)    // 23040
#define AT_SMEM   ((AT_VOFF + 3 * AT_TILEH) * 2)   // 73728 B

__global__ __launch_bounds__(256, 2) void attn_h(float* __restrict__ out)
{
    extern __shared__ __half smh[];
    const uint32_t smb = smem_u32(smh);

    const int qt = 15 - (int)blockIdx.x;
    const int bh = blockIdx.y;
    const int b  = bh >> 4;
    const int h  = bh & 15;
    const int q0 = qt * 128;

    const __half* qg = g_qh + (size_t)bh * NT * NDK;
    const __half* kg = g_kh + (size_t)bh * NT * NDK;
    const __half* vg = g_vt + (size_t)bh * NDK * NT;

    const int tid  = threadIdx.x;
    const int wid  = tid >> 5;
    const int lane = tid & 31;
    const int qr   = lane >> 2;
    const int qc   = lane & 3;

    const int row_ = tid >> 3;
    const int ch_  = (tid & 7) * 8;

    const uint32_t lmoff = (uint32_t)(((lane & 7) * AT_STRIDE + (lane >> 3) * 8) * 2);

    // Q tile (group 0)
    #pragma unroll
    for (int j = 0; j < 4; j++) {
        int row = row_ + j * 32;
        CP_ASYNC16(smb + (uint32_t)(row * AT_STRIDE + ch_) * 2,
                   qg + (size_t)(q0 + row) * NDK + ch_);
    }
    CP_COMMIT;

    // K/V tile 0 into buffer 0 (group 1)
    #pragma unroll
    for (int j = 0; j < 2; j++) {
        int row = row_ + j * 32;
        CP_ASYNC16(smb + (uint32_t)(AT_KOFF + row * AT_STRIDE + ch_) * 2,
                   kg + (size_t)row * NDK + ch_);
        CP_ASYNC16(smb + (uint32_t)(AT_VOFF + row * AT_STRIDE + ch_) * 2,
                   vg + (size_t)row * NT + ch_);
    }
    CP_COMMIT;

    CP_WAIT(1);            // Q visible
    __syncthreads();

    uint32_t qf[4][4];
    {
        const __half* Qw = smh + (wid * 16) * AT_STRIDE;
        #pragma unroll
        for (int ks = 0; ks < 4; ks++) {
            const __half* p = Qw + qr * AT_STRIDE + ks * 16 + 2 * qc;
            qf[ks][0] = *(const uint32_t*)(p);
            qf[ks][1] = *(const uint32_t*)(p + 8 * AT_STRIDE);
            qf[ks][2] = *(const uint32_t*)(p + 8);
            qf[ks][3] = *(const uint32_t*)(p + 8 * AT_STRIDE + 8);
        }
    }

    float o[8][4];
    #pragma unroll
    for (int ni = 0; ni < 8; ni++)
        #pragma unroll
        for (int v = 0; v < 4; v++) o[ni][v] = 0.0f;
    float lsum[4] = {0.0f, 0.0f, 0.0f, 0.0f};
    float m0 = -INFINITY, m1 = -INFINITY;

    const uint32_t bones[2] = {0x3C003C00u, 0x3C003C00u};   // fp16 1.0 pairs
    const int ntiles = 2 * qt + 2;

    int cur = 0, nxt = 1;
    for (int kt = 0; kt < ntiles; kt++) {
        if (kt + 1 < ntiles) {
            const int s1 = (kt + 1) * 64;
            const uint32_t kb = AT_KOFF + (uint32_t)(nxt * AT_TILEH);
            const uint32_t vb = AT_VOFF + (uint32_t)(nxt * AT_TILEH);
            #pragma unroll
            for (int j = 0; j < 2; j++) {
                int row = row_ + j * 32;
                CP_ASYNC16(smb + (kb + row * AT_STRIDE + ch_) * 2,
                           kg + (size_t)(s1 + row) * NDK + ch_);
                CP_ASYNC16(smb + (vb + row * AT_STRIDE + ch_) * 2,
                           vg + (size_t)row * NT + s1 + ch_);
            }
            CP_COMMIT;
            CP_WAIT(1);
        } else {
            CP_WAIT(0);
        }
        __syncthreads();     // single barrier per tile (3-deep buffer)

        const uint32_t Kb = smb + (AT_KOFF + cur * AT_TILEH) * 2 + lmoff;
        const uint32_t Vb = smb + (AT_VOFF + cur * AT_TILEH) * 2 + lmoff;
        const int s0 = kt * 64;

        // ---- S (log2-scaled) = Q' K^T ----
        float sc[8][4];
        #pragma unroll
        for (int ni = 0; ni < 8; ni++)
            #pragma unroll
            for (int v = 0; v < 4; v++) sc[ni][v] = 0.0f;

        #pragma unroll
        for (int ni = 0; ni < 8; ni++) {
            const uint32_t base = Kb + (uint32_t)(ni * 8 * AT_STRIDE * 2);
            uint32_t kf[4];
            ldsm_x4(kf, base);
            mma_f16(sc[ni], qf[0], kf);
            mma_f16(sc[ni], qf[1], kf + 2);
            ldsm_x4(kf, base + 64);
            mma_f16(sc[ni], qf[2], kf);
            mma_f16(sc[ni], qf[3], kf + 2);
        }

        // ---- causal mask ----
        if (kt >= 2 * qt) {
            const int r0g = q0 + wid * 16 + qr;
            const int r1g = r0g + 8;
            #pragma unroll
            for (int ni = 0; ni < 8; ni++) {
                const int c = s0 + ni * 8 + 2 * qc;
                if (c     > r0g) sc[ni][0] = -INFINITY;
                if (c + 1 > r0g) sc[ni][1] = -INFINITY;
                if (c     > r1g) sc[ni][2] = -INFINITY;
                if (c + 1 > r1g) sc[ni][3] = -INFINITY;
            }
        }

        // ---- row max (quad shuffles) ----
        float rmax0 = sc[0][0], rmax1 = sc[0][2];
        #pragma unroll
        for (int ni = 0; ni < 8; ni++) {
            rmax0 = fmaxf(rmax0, fmaxf(sc[ni][0], sc[ni][1]));
            rmax1 = fmaxf(rmax1, fmaxf(sc[ni][2], sc[ni][3]));
        }
        rmax0 = fmaxf(rmax0, __shfl_xor_sync(0xffffffffu, rmax0, 1));
        rmax0 = fmaxf(rmax0, __shfl_xor_sync(0xffffffffu, rmax0, 2));
        rmax1 = fmaxf(rmax1, __shfl_xor_sync(0xffffffffu, rmax1, 1));
        rmax1 = fmaxf(rmax1, __shfl_xor_sync(0xffffffffu, rmax1, 2));

        const float mn0 = fmaxf(m0, rmax0);
        const float mn1 = fmaxf(m1, rmax1);
        const float a0  = exp2f(m0 - mn0);
        const float a1  = exp2f(m1 - mn1);
        m0 = mn0;  m1 = mn1;

        #pragma unroll
        for (int ni = 0; ni < 8; ni++) {
            o[ni][0] *= a0; o[ni][1] *= a0;
            o[ni][2] *= a1; o[ni][3] *= a1;
        }
        lsum[0] *= a0;  lsum[2] *= a1;

        // ---- P = exp2(S - m) in fp16x2, directly as PV A fragments ----
        uint32_t pf[4][4];
        #pragma unroll
        for (int ks = 0; ks < 4; ks++) {
            pf[ks][0] = h2e(sc[2*ks    ][0] - mn0, sc[2*ks    ][1] - mn0);
            pf[ks][1] = h2e(sc[2*ks    ][2] - mn1, sc[2*ks    ][3] - mn1);
            pf[ks][2] = h2e(sc[2*ks + 1][0] - mn0, sc[2*ks + 1][1] - mn0);
            pf[ks][3] = h2e(sc[2*ks + 1][2] - mn1, sc[2*ks + 1][3] - mn1);
        }

        // ---- row sums via ones-column mma (no shuffles) ----
        mma_f16(lsum, pf[0], bones);
        mma_f16(lsum, pf[1], bones);
        mma_f16(lsum, pf[2], bones);
        mma_f16(lsum, pf[3], bones);

        // ---- O += P V ----
        #pragma unroll
        for (int ni = 0; ni < 8; ni++) {
            const uint32_t base = Vb + (uint32_t)(ni * 8 * AT_STRIDE * 2);
            uint32_t vf[4];
            ldsm_x4(vf, base);
            mma_f16(o[ni], pf[0], vf);
            mma_f16(o[ni], pf[1], vf + 2);
            ldsm_x4(vf, base + 64);
            mma_f16(o[ni], pf[2], vf);
            mma_f16(o[ni], pf[3], vf + 2);
        }

        cur = nxt;
        nxt = (nxt == 2) ? 0 : nxt + 1;
    }

    // ---- finalize (l already in every lane) + write out ----
    const float inv0 = 1.0f / lsum[0];
    const float inv1 = 1.0f / lsum[2];
    const int t0 = q0 + wid * 16 + qr;
    size_t base0 = ((size_t)b * NT + t0) * (NH * NDK) + h * NDK;
    size_t base1 = base0 + 8 * (size_t)(NH * NDK);
    #pragma unroll
    for (int ni = 0; ni < 8; ni++) {
        const int n = ni * 8 + 2 * qc;
        *(float2*)&out[base0 + n] = make_float2(o[ni][0] * inv0, o[ni][1] * inv0);
        *(float2*)&out[base1 + n] = make_float2(o[ni][2] * inv1, o[ni][3] * inv1);
    }
}

// ---------------------------------------------------------------------------
extern "C" void kernel_launch(void* const* d_in, const int* in_sizes, int n_in,
                              void* d_out, int out_size)
{
    (void)in_sizes; (void)n_in; (void)out_size;
    const float* x  = (const float*)d_in[0];
    const float* Wq = (const float*)d_in[1];
    const float* Wk = (const float*)d_in[2];
    const float* Wv = (const float*)d_in[3];
    float* out = (float*)d_out;

    cudaFuncSetAttribute(proj_h,
                         cudaFuncAttributeMaxDynamicSharedMemorySize, PJ_SMEM);
    cudaFuncSetAttribute(attn_h,
                         cudaFuncAttributeMaxDynamicSharedMemorySize, AT_SMEM);

    convert_x<<<NB * NT * NDM / 1024, 256>>>(x);
    convert_w<<<dim3(NDM / 32, NDK / 32, 48), dim3(32, 8)>>>(Wq, Wk, Wv);

    proj_h<<<dim3(NB * NT / 128, 24), 256, PJ_SMEM>>>();

    attn_h<<<dim3(NT / 128, NB * NH), 256, AT_SMEM>>>(out);
}

// round 12
// speedup vs baseline: 6.9570x; 1.0414x over previous
#include <cuda_runtime.h>
#include <cuda_fp16.h>
#include <math.h>
#include <stdint.h>

#define NB 4
#define NT 2048
#define NDM 1024
#define NH 16
#define NDK 64

// fp16 staging buffers
__device__ __half g_xh[NB*NT*NDM];        // x in fp16            [b*t][d]
__device__ __half g_wth[3*NH*NDK*NDM];    // W fp16 transposed    [z*1024+n][d]
__device__ __half g_qh[NB*NH*NT*NDK];     // Q*0.125*log2e fp16   [bh][t][d]
__device__ __half g_kh[NB*NH*NT*NDK];     // K fp16               [bh][t][d]
__device__ __half g_vt[NB*NH*NDK*NT];     // V fp16 TRANSPOSED    [bh][d][t]

__device__ __forceinline__ void mma_f16(float* c, const uint32_t* a, const uint32_t* b) {
    asm volatile("mma.sync.aligned.m16n8k16.row.col.f32.f16.f16.f32 "
                 "{%0,%1,%2,%3}, {%4,%5,%6,%7}, {%8,%9}, {%0,%1,%2,%3};"
                 : "+f"(c[0]), "+f"(c[1]), "+f"(c[2]), "+f"(c[3])
                 : "r"(a[0]), "r"(a[1]), "r"(a[2]), "r"(a[3]),
                   "r"(b[0]), "r"(b[1]));
}
__device__ __forceinline__ void ldsm_x4(uint32_t* d, uint32_t addr) {
    asm volatile("ldmatrix.sync.aligned.m8n8.x4.shared.b16 {%0,%1,%2,%3}, [%4];"
                 : "=r"(d[0]), "=r"(d[1]), "=r"(d[2]), "=r"(d[3]) : "r"(addr));
}
__device__ __forceinline__ uint32_t smem_u32(const void* p) {
    uint32_t a;
    asm("{ .reg .u64 t; cvta.to.shared.u64 t, %1; cvt.u32.u64 %0, t; }"
        : "=r"(a) : "l"(p));
    return a;
}
__device__ __forceinline__ uint32_t h2e(float lo, float hi) {
    __half2 h = h2exp2(__floats2half2_rn(lo, hi));
    return *(uint32_t*)&h;
}
#define CP_ASYNC16(dst, src) \
    asm volatile("cp.async.cg.shared.global [%0], [%1], 16;" \
                 :: "r"(dst), "l"(src) : "memory")
#define CP_COMMIT  asm volatile("cp.async.commit_group;" ::: "memory")
#define CP_WAIT(n) asm volatile("cp.async.wait_group %0;" :: "n"(n) : "memory")

// ---------------------------------------------------------------------------
// Pre-pass 1: x -> fp16
// ---------------------------------------------------------------------------
__global__ __launch_bounds__(256) void convert_x(const float* __restrict__ x)
{
    const int i = ((int)blockIdx.x * 256 + (int)threadIdx.x) * 4;
    float4 v = *(const float4*)&x[i];
    *(__half2*)&g_xh[i]     = __floats2half2_rn(v.x, v.y);
    *(__half2*)&g_xh[i + 2] = __floats2half2_rn(v.z, v.w);
}

// ---------------------------------------------------------------------------
// Pre-pass 2: W[h][d][n] -> Wt fp16 [z*1024 + h*64 + n][d]
// ---------------------------------------------------------------------------
__global__ __launch_bounds__(256) void convert_w(
    const float* __restrict__ Wq, const float* __restrict__ Wk,
    const float* __restrict__ Wv)
{
    __shared__ float tile[32][33];
    const int zh = blockIdx.z;
    const int z = zh >> 4, h = zh & 15;
    const float* W = (z == 0 ? Wq : z == 1 ? Wk : Wv) + (size_t)h * NDM * NDK;
    const int d0 = blockIdx.x * 32;
    const int n0 = blockIdx.y * 32;
    const int tx = threadIdx.x, ty = threadIdx.y;

    #pragma unroll
    for (int j = 0; j < 4; j++)
        tile[ty + j * 8][tx] = W[(size_t)(d0 + ty + j * 8) * NDK + n0 + tx];
    __syncthreads();
    __half* dst = g_wth + ((size_t)(z * NH + h) * NDK) * NDM;
    #pragma unroll
    for (int j = 0; j < 4; j++)
        dst[(size_t)(n0 + ty + j * 8) * NDM + d0 + tx] =
            __float2half_rn(tile[tx][ty + j * 8]);
}

// ---------------------------------------------------------------------------
// Projection GEMM on fp16 m16n8k16 + ldmatrix (unchanged from round 10).
// ---------------------------------------------------------------------------
#define PJ_STRIDE 72
#define PJ_TILE   (128 * PJ_STRIDE)
#define PJ_STAGE  (2 * PJ_TILE)
#define PJ_SMEM   (2 * PJ_STAGE * 2)
#define VST 136

__global__ __launch_bounds__(256, 2) void proj_h()
{
    extern __shared__ __half smh[];
    const uint32_t smb = smem_u32(smh);

    const int m0 = blockIdx.x * 128;
    const int by = blockIdx.y;
    const int z  = by >> 3;
    const int n0 = (by & 7) * 128;
    const __half* wt = g_wth + (size_t)(z * 1024 + n0) * NDM;

    const int tid  = threadIdx.x;
    const int lane = tid & 31;
    const int qr   = lane >> 2;
    const int qc   = lane & 3;
    const int wid  = tid >> 5;
    const int wr   = wid >> 1;
    const int wc   = wid & 1;

    const int row_ = tid >> 3;
    const int ch_  = (tid & 7) * 8;

    const uint32_t aoff = (uint32_t)(((wr * 32 + (lane & 15)) * PJ_STRIDE
                                      + (lane >> 4) * 8) * 2);
    const uint32_t boff = (uint32_t)(((wc * 64 + (lane & 7)) * PJ_STRIDE
                                      + (lane >> 3) * 8) * 2);

    float acc[2][8][4];
    #pragma unroll
    for (int mi = 0; mi < 2; mi++)
        #pragma unroll
        for (int ni = 0; ni < 8; ni++)
            #pragma unroll
            for (int v = 0; v < 4; v++) acc[mi][ni][v] = 0.0f;

    #pragma unroll
    for (int j = 0; j < 4; j++) {
        int row = row_ + j * 32;
        CP_ASYNC16(smb + (uint32_t)(row * PJ_STRIDE + ch_) * 2,
                   g_xh + (size_t)(m0 + row) * NDM + ch_);
        CP_ASYNC16(smb + (uint32_t)(PJ_TILE + row * PJ_STRIDE + ch_) * 2,
                   wt + (size_t)row * NDM + ch_);
    }
    CP_COMMIT;

    for (int s = 0; s < 16; s++) {
        if (s + 1 < 16) {
            const int k1 = (s + 1) * 64;
            const uint32_t sb = (uint32_t)(((s + 1) & 1) * PJ_STAGE);
            #pragma unroll
            for (int j = 0; j < 4; j++) {
                int row = row_ + j * 32;
                CP_ASYNC16(smb + (sb + row * PJ_STRIDE + ch_) * 2,
                           g_xh + (size_t)(m0 + row) * NDM + k1 + ch_);
                CP_ASYNC16(smb + (sb + PJ_TILE + row * PJ_STRIDE + ch_) * 2,
                           wt + (size_t)row * NDM + k1 + ch_);
            }
            CP_COMMIT;
            CP_WAIT(1);
        } else {
            CP_WAIT(0);
        }
        __syncthreads();

        const uint32_t Ab = smb + (uint32_t)((s & 1) * PJ_STAGE) * 2 + aoff;
        const uint32_t Bb = smb + (uint32_t)((s & 1) * PJ_STAGE + PJ_TILE) * 2 + boff;

        #pragma unroll
        for (int ks2 = 0; ks2 < 2; ks2++) {
            uint32_t bfr[8][4];
            #pragma unroll
            for (int ni = 0; ni < 8; ni++)
                ldsm_x4(bfr[ni], Bb + (uint32_t)(ni * 8 * PJ_STRIDE * 2 + ks2 * 64));
            #pragma unroll
            for (int ks = 0; ks < 2; ks++) {
                uint32_t af[2][4];
                const uint32_t ka = (uint32_t)((ks2 * 2 + ks) * 32);
                ldsm_x4(af[0], Ab + ka);
                ldsm_x4(af[1], Ab + (uint32_t)(16 * PJ_STRIDE * 2) + ka);
                #pragma unroll
                for (int mi = 0; mi < 2; mi++)
                    #pragma unroll
                    for (int ni = 0; ni < 8; ni++)
                        mma_f16(acc[mi][ni], af[mi], bfr[ni] + 2 * ks);
            }
        }
        __syncthreads();
    }

    const float QSC = 0.125f * 1.44269504088896340736f;
    const int b     = m0 >> 11;
    const int tbase = m0 & 2047;

    if (z < 2) {
        #pragma unroll
        for (int mi = 0; mi < 2; mi++) {
            const int t0 = tbase + wr * 32 + mi * 16 + qr;
            #pragma unroll
            for (int ni = 0; ni < 8; ni++) {
                const int ncta = wc * 64 + ni * 8 + 2 * qc;
                const int ng   = n0 + ncta;
                const int h    = ng >> 6;
                const int d    = ng & 63;
                const size_t bh = (size_t)(b * NH + h);
                if (z == 0) {
                    *(__half2*)&g_qh[(bh * NT + t0) * NDK + d] =
                        __floats2half2_rn(acc[mi][ni][0] * QSC, acc[mi][ni][1] * QSC);
                    *(__half2*)&g_qh[(bh * NT + t0 + 8) * NDK + d] =
                        __floats2half2_rn(acc[mi][ni][2] * QSC, acc[mi][ni][3] * QSC);
                } else {
                    *(__half2*)&g_kh[(bh * NT + t0) * NDK + d] =
                        __floats2half2_rn(acc[mi][ni][0], acc[mi][ni][1]);
                    *(__half2*)&g_kh[(bh * NT + t0 + 8) * NDK + d] =
                        __floats2half2_rn(acc[mi][ni][2], acc[mi][ni][3]);
                }
            }
        }
    } else {
        #pragma unroll
        for (int mi = 0; mi < 2; mi++) {
            const int tl = wr * 32 + mi * 16 + qr;
            #pragma unroll
            for (int ni = 0; ni < 8; ni++) {
                const int dl = wc * 64 + ni * 8 + 2 * qc;
                smh[(dl    ) * VST + tl    ] = __float2half_rn(acc[mi][ni][0]);
                smh[(dl + 1) * VST + tl    ] = __float2half_rn(acc[mi][ni][1]);
                smh[(dl    ) * VST + tl + 8] = __float2half_rn(acc[mi][ni][2]);
                smh[(dl + 1) * VST + tl + 8] = __float2half_rn(acc[mi][ni][3]);
            }
        }
        __syncthreads();
        const int cr = tid >> 4;
        const int cc = (tid & 15) * 8;
        #pragma unroll
        for (int j = 0; j < 8; j++) {
            const int r  = cr + j * 16;
            const int ng = n0 + r;
            const int h  = ng >> 6;
            const int d  = ng & 63;
            __half* dst = g_vt + ((size_t)(b * NH + h) * NDK + d) * NT + tbase + cc;
            *(float4*)dst = *(const float4*)&smh[r * VST + cc];
        }
    }
}

// ---------------------------------------------------------------------------
// Flash attention v4: 64-query CTAs (128 threads, 4 warps), occupancy 3.
// Triple-buffered K/V (one barrier/tile), row sums via ones-column mma,
// f16x2 exp2 for P. Smem halves: Q 64x72 | K 3x64x72 | V 3x64x72 = 32256.
// ---------------------------------------------------------------------------
#define AT_STRIDE 72
#define AT_TILEH  (64 * AT_STRIDE)            // 4608 halves per tile
#define AT_KOFF   (64 * AT_STRIDE)            // 4608 (after Q)
#define AT_VOFF   (AT_KOFF + 3 * AT_TILEH)    // 18432
#define AT_SMEM   ((AT_VOFF + 3 * AT_TILEH) * 2)   // 64512 B

__global__ __launch_bounds__(128, 3) void attn_h(float* __restrict__ out)
{
    extern __shared__ __half smh[];
    const uint32_t smb = smem_u32(smh);

    const int qt = 31 - (int)blockIdx.x;      // big tiles first
    const int bh = blockIdx.y;
    const int b  = bh >> 4;
    const int h  = bh & 15;
    const int q0 = qt * 64;

    const __half* qg = g_qh + (size_t)bh * NT * NDK;
    const __half* kg = g_kh + (size_t)bh * NT * NDK;
    const __half* vg = g_vt + (size_t)bh * NDK * NT;

    const int tid  = threadIdx.x;
    const int wid  = tid >> 5;                // 0..3
    const int lane = tid & 31;
    const int qr   = lane >> 2;
    const int qc   = lane & 3;

    const int row_ = tid >> 1;                // 0..63 (Q: 1 row per 2 threads? no)
    // 64x64 halves = 512 16B-chunks; 128 threads x 4 chunks.
    // chunk q = tid + j*128: row = q>>3 (0..63), ch = (q&7)*8
    const int ch_  = (tid & 7) * 8;
    const int krow_ = tid >> 3;               // 0..15 (+16j)

    const uint32_t lmoff = (uint32_t)(((lane & 7) * AT_STRIDE + (lane >> 3) * 8) * 2);

    // Q tile (group 0): 64 rows
    #pragma unroll
    for (int j = 0; j < 4; j++) {
        int row = krow_ + j * 16;
        CP_ASYNC16(smb + (uint32_t)(row * AT_STRIDE + ch_) * 2,
                   qg + (size_t)(q0 + row) * NDK + ch_);
    }
    CP_COMMIT;

    // K/V tile 0 into buffer 0 (group 1)
    #pragma unroll
    for (int j = 0; j < 4; j++) {
        int row = krow_ + j * 16;
        CP_ASYNC16(smb + (uint32_t)(AT_KOFF + row * AT_STRIDE + ch_) * 2,
                   kg + (size_t)row * NDK + ch_);
        CP_ASYNC16(smb + (uint32_t)(AT_VOFF + row * AT_STRIDE + ch_) * 2,
                   vg + (size_t)row * NT + ch_);
    }
    CP_COMMIT;

    CP_WAIT(1);            // Q visible
    __syncthreads();

    uint32_t qf[4][4];
    {
        const __half* Qw = smh + (wid * 16) * AT_STRIDE;
        #pragma unroll
        for (int ks = 0; ks < 4; ks++) {
            const __half* p = Qw + qr * AT_STRIDE + ks * 16 + 2 * qc;
            qf[ks][0] = *(const uint32_t*)(p);
            qf[ks][1] = *(const uint32_t*)(p + 8 * AT_STRIDE);
            qf[ks][2] = *(const uint32_t*)(p + 8);
            qf[ks][3] = *(const uint32_t*)(p + 8 * AT_STRIDE + 8);
        }
    }

    float o[8][4];
    #pragma unroll
    for (int ni = 0; ni < 8; ni++)
        #pragma unroll
        for (int v = 0; v < 4; v++) o[ni][v] = 0.0f;
    float lsum[4] = {0.0f, 0.0f, 0.0f, 0.0f};
    float m0 = -INFINITY, m1 = -INFINITY;

    const uint32_t bones[2] = {0x3C003C00u, 0x3C003C00u};   // fp16 1.0 pairs
    const int ntiles = qt + 1;

    int cur = 0, nxt = 1;
    for (int kt = 0; kt < ntiles; kt++) {
        if (kt + 1 < ntiles) {
            const int s1 = (kt + 1) * 64;
            const uint32_t kb = AT_KOFF + (uint32_t)(nxt * AT_TILEH);
            const uint32_t vb = AT_VOFF + (uint32_t)(nxt * AT_TILEH);
            #pragma unroll
            for (int j = 0; j < 4; j++) {
                int row = krow_ + j * 16;
                CP_ASYNC16(smb + (kb + row * AT_STRIDE + ch_) * 2,
                           kg + (size_t)(s1 + row) * NDK + ch_);
                CP_ASYNC16(smb + (vb + row * AT_STRIDE + ch_) * 2,
                           vg + (size_t)row * NT + s1 + ch_);
            }
            CP_COMMIT;
            CP_WAIT(1);
        } else {
            CP_WAIT(0);
        }
        __syncthreads();     // single barrier per tile (3-deep buffer)

        const uint32_t Kb = smb + (AT_KOFF + cur * AT_TILEH) * 2 + lmoff;
        const uint32_t Vb = smb + (AT_VOFF + cur * AT_TILEH) * 2 + lmoff;
        const int s0 = kt * 64;

        // ---- S (log2-scaled) = Q' K^T ----
        float sc[8][4];
        #pragma unroll
        for (int ni = 0; ni < 8; ni++)
            #pragma unroll
            for (int v = 0; v < 4; v++) sc[ni][v] = 0.0f;

        #pragma unroll
        for (int ni = 0; ni < 8; ni++) {
            const uint32_t base = Kb + (uint32_t)(ni * 8 * AT_STRIDE * 2);
            uint32_t kf[4];
            ldsm_x4(kf, base);
            mma_f16(sc[ni], qf[0], kf);
            mma_f16(sc[ni], qf[1], kf + 2);
            ldsm_x4(kf, base + 64);
            mma_f16(sc[ni], qf[2], kf);
            mma_f16(sc[ni], qf[3], kf + 2);
        }

        // ---- causal mask (diagonal tile only) ----
        if (kt == qt) {
            const int r0g = q0 + wid * 16 + qr;
            const int r1g = r0g + 8;
            #pragma unroll
            for (int ni = 0; ni < 8; ni++) {
                const int c = s0 + ni * 8 + 2 * qc;
                if (c     > r0g) sc[ni][0] = -INFINITY;
                if (c + 1 > r0g) sc[ni][1] = -INFINITY;
                if (c     > r1g) sc[ni][2] = -INFINITY;
                if (c + 1 > r1g) sc[ni][3] = -INFINITY;
            }
        }

        // ---- row max (quad shuffles) ----
        float rmax0 = sc[0][0], rmax1 = sc[0][2];
        #pragma unroll
        for (int ni = 0; ni < 8; ni++) {
            rmax0 = fmaxf(rmax0, fmaxf(sc[ni][0], sc[ni][1]));
            rmax1 = fmaxf(rmax1, fmaxf(sc[ni][2], sc[ni][3]));
        }
        rmax0 = fmaxf(rmax0, __shfl_xor_sync(0xffffffffu, rmax0, 1));
        rmax0 = fmaxf(rmax0, __shfl_xor_sync(0xffffffffu, rmax0, 2));
        rmax1 = fmaxf(rmax1, __shfl_xor_sync(0xffffffffu, rmax1, 1));
        rmax1 = fmaxf(rmax1, __shfl_xor_sync(0xffffffffu, rmax1, 2));

        const float mn0 = fmaxf(m0, rmax0);
        const float mn1 = fmaxf(m1, rmax1);
        const float a0  = exp2f(m0 - mn0);
        const float a1  = exp2f(m1 - mn1);
        m0 = mn0;  m1 = mn1;

        #pragma unroll
        for (int ni = 0; ni < 8; ni++) {
            o[ni][0] *= a0; o[ni][1] *= a0;
            o[ni][2] *= a1; o[ni][3] *= a1;
        }
        lsum[0] *= a0;  lsum[2] *= a1;

        // ---- P = exp2(S - m) in fp16x2, directly as PV A fragments ----
        uint32_t pf[4][4];
        #pragma unroll
        for (int ks = 0; ks < 4; ks++) {
            pf[ks][0] = h2e(sc[2*ks    ][0] - mn0, sc[2*ks    ][1] - mn0);
            pf[ks][1] = h2e(sc[2*ks    ][2] - mn1, sc[2*ks    ][3] - mn1);
            pf[ks][2] = h2e(sc[2*ks + 1][0] - mn0, sc[2*ks + 1][1] - mn0);
            pf[ks][3] = h2e(sc[2*ks + 1][2] - mn1, sc[2*ks + 1][3] - mn1);
        }

        // ---- row sums via ones-column mma ----
        mma_f16(lsum, pf[0], bones);
        mma_f16(lsum, pf[1], bones);
        mma_f16(lsum, pf[2], bones);
        mma_f16(lsum, pf[3], bones);

        // ---- O += P V ----
        #pragma unroll
        for (int ni = 0; ni < 8; ni++) {
            const uint32_t base = Vb + (uint32_t)(ni * 8 * AT_STRIDE * 2);
            uint32_t vf[4];
            ldsm_x4(vf, base);
            mma_f16(o[ni], pf[0], vf);
            mma_f16(o[ni], pf[1], vf + 2);
            ldsm_x4(vf, base + 64);
            mma_f16(o[ni], pf[2], vf);
            mma_f16(o[ni], pf[3], vf + 2);
        }

        cur = nxt;
        nxt = (nxt == 2) ? 0 : nxt + 1;
    }

    // ---- finalize + write out ----
    const float inv0 = 1.0f / lsum[0];
    const float inv1 = 1.0f / lsum[2];
    const int t0 = q0 + wid * 16 + qr;
    size_t base0 = ((size_t)b * NT + t0) * (NH * NDK) + h * NDK;
    size_t base1 = base0 + 8 * (size_t)(NH * NDK);
    #pragma unroll
    for (int ni = 0; ni < 8; ni++) {
        const int n = ni * 8 + 2 * qc;
        *(float2*)&out[base0 + n] = make_float2(o[ni][0] * inv0, o[ni][1] * inv0);
        *(float2*)&out[base1 + n] = make_float2(o[ni][2] * inv1, o[ni][3] * inv1);
    }
}

// ---------------------------------------------------------------------------
extern "C" void kernel_launch(void* const* d_in, const int* in_sizes, int n_in,
                              void* d_out, int out_size)
{
    (void)in_sizes; (void)n_in; (void)out_size;
    const float* x  = (const float*)d_in[0];
    const float* Wq = (const float*)d_in[1];
    const float* Wk = (const float*)d_in[2];
    const float* Wv = (const float*)d_in[3];
    float* out = (float*)d_out;

    cudaFuncSetAttribute(proj_h,
                         cudaFuncAttributeMaxDynamicSharedMemorySize, PJ_SMEM);
    cudaFuncSetAttribute(attn_h,
                         cudaFuncAttributeMaxDynamicSharedMemorySize, AT_SMEM);

    convert_x<<<NB * NT * NDM / 1024, 256>>>(x);
    convert_w<<<dim3(NDM / 32, NDK / 32, 48), dim3(32, 8)>>>(Wq, Wk, Wv);

    proj_h<<<dim3(NB * NT / 128, 24), 256, PJ_SMEM>>>();

    attn_h<<<dim3(NT / 64, NB * NH), 128, AT_SMEM>>>(out);
}

// round 13
// speedup vs baseline: 7.2958x; 1.0487x over previous
#include <cuda_runtime.h>
#include <cuda_fp16.h>
#include <math.h>
#include <stdint.h>

#define NB 4
#define NT 2048
#define NDM 1024
#define NH 16
#define NDK 64

// fp16 staging buffers
__device__ __half g_xh[NB*NT*NDM];        // x in fp16            [b*t][d]
__device__ __half g_wth[3*NH*NDK*NDM];    // W fp16 transposed    [z*1024+n][d]
__device__ __half g_qh[NB*NH*NT*NDK];     // Q*0.125*log2e fp16   [bh][t][d]
__device__ __half g_kh[NB*NH*NT*NDK];     // K fp16               [bh][t][d]
__device__ __half g_vt[NB*NH*NDK*NT];     // V fp16 TRANSPOSED    [bh][d][t]

__device__ __forceinline__ void mma_f16(float* c, const uint32_t* a, const uint32_t* b) {
    asm volatile("mma.sync.aligned.m16n8k16.row.col.f32.f16.f16.f32 "
                 "{%0,%1,%2,%3}, {%4,%5,%6,%7}, {%8,%9}, {%0,%1,%2,%3};"
                 : "+f"(c[0]), "+f"(c[1]), "+f"(c[2]), "+f"(c[3])
                 : "r"(a[0]), "r"(a[1]), "r"(a[2]), "r"(a[3]),
                   "r"(b[0]), "r"(b[1]));
}
__device__ __forceinline__ void ldsm_x4(uint32_t* d, uint32_t addr) {
    asm volatile("ldmatrix.sync.aligned.m8n8.x4.shared.b16 {%0,%1,%2,%3}, [%4];"
                 : "=r"(d[0]), "=r"(d[1]), "=r"(d[2]), "=r"(d[3]) : "r"(addr));
}
__device__ __forceinline__ uint32_t smem_u32(const void* p) {
    uint32_t a;
    asm("{ .reg .u64 t; cvta.to.shared.u64 t, %1; cvt.u32.u64 %0, t; }"
        : "=r"(a) : "l"(p));
    return a;
}
__device__ __forceinline__ uint32_t h2e(float lo, float hi) {
    __half2 h = h2exp2(__floats2half2_rn(lo, hi));
    return *(uint32_t*)&h;
}
#define CP_ASYNC16(dst, src) \
    asm volatile("cp.async.cg.shared.global [%0], [%1], 16;" \
                 :: "r"(dst), "l"(src) : "memory")
#define CP_COMMIT  asm volatile("cp.async.commit_group;" ::: "memory")
#define CP_WAIT(n) asm volatile("cp.async.wait_group %0;" :: "n"(n) : "memory")

// ---------------------------------------------------------------------------
// Pre-pass 1: x -> fp16
// ---------------------------------------------------------------------------
__global__ __launch_bounds__(256) void convert_x(const float* __restrict__ x)
{
    const int i = ((int)blockIdx.x * 256 + (int)threadIdx.x) * 4;
    float4 v = *(const float4*)&x[i];
    *(__half2*)&g_xh[i]     = __floats2half2_rn(v.x, v.y);
    *(__half2*)&g_xh[i + 2] = __floats2half2_rn(v.z, v.w);
}

// ---------------------------------------------------------------------------
// Pre-pass 2: W[h][d][n] -> Wt fp16 [z*1024 + h*64 + n][d]
// ---------------------------------------------------------------------------
__global__ __launch_bounds__(256) void convert_w(
    const float* __restrict__ Wq, const float* __restrict__ Wk,
    const float* __restrict__ Wv)
{
    __shared__ float tile[32][33];
    const int zh = blockIdx.z;
    const int z = zh >> 4, h = zh & 15;
    const float* W = (z == 0 ? Wq : z == 1 ? Wk : Wv) + (size_t)h * NDM * NDK;
    const int d0 = blockIdx.x * 32;
    const int n0 = blockIdx.y * 32;
    const int tx = threadIdx.x, ty = threadIdx.y;

    #pragma unroll
    for (int j = 0; j < 4; j++)
        tile[ty + j * 8][tx] = W[(size_t)(d0 + ty + j * 8) * NDK + n0 + tx];
    __syncthreads();
    __half* dst = g_wth + ((size_t)(z * NH + h) * NDK) * NDM;
    #pragma unroll
    for (int j = 0; j < 4; j++)
        dst[(size_t)(n0 + ty + j * 8) * NDM + d0 + tx] =
            __float2half_rn(tile[tx][ty + j * 8]);
}

// ---------------------------------------------------------------------------
// Projection GEMM v3: 128 threads, 4 warps (2x2), warp tile 64x64
// (4mi x 8ni), BK=64 double-buffered. 32 ldsm serve 128 mma per warp-stage.
// ---------------------------------------------------------------------------
#define PJ_STRIDE 72
#define PJ_TILE   (128 * PJ_STRIDE)
#define PJ_STAGE  (2 * PJ_TILE)
#define PJ_SMEM   (2 * PJ_STAGE * 2)     // 73728 B
#define VST 136

__global__ __launch_bounds__(128, 2) void proj_h()
{
    extern __shared__ __half smh[];
    const uint32_t smb = smem_u32(smh);

    const int m0 = blockIdx.x * 128;
    const int by = blockIdx.y;
    const int z  = by >> 3;
    const int n0 = (by & 7) * 128;
    const __half* wt = g_wth + (size_t)(z * 1024 + n0) * NDM;

    const int tid  = threadIdx.x;
    const int lane = tid & 31;
    const int qr   = lane >> 2;
    const int qc   = lane & 3;
    const int wid  = tid >> 5;
    const int wr   = wid >> 1;           // 0..1 : rows wr*64
    const int wc   = wid & 1;            // 0..1 : cols wc*64

    const int ch_  = (tid & 7) * 8;      // 16B chunk offset in halves

    const uint32_t aoff = (uint32_t)(((wr * 64 + (lane & 15)) * PJ_STRIDE
                                      + (lane >> 4) * 8) * 2);
    const uint32_t boff = (uint32_t)(((wc * 64 + (lane & 7)) * PJ_STRIDE
                                      + (lane >> 3) * 8) * 2);

    float acc[4][8][4];
    #pragma unroll
    for (int mi = 0; mi < 4; mi++)
        #pragma unroll
        for (int ni = 0; ni < 8; ni++)
            #pragma unroll
            for (int v = 0; v < 4; v++) acc[mi][ni][v] = 0.0f;

    // prologue: stage 0 — A and B tiles are 128x64 halves = 1024 chunks each
    #pragma unroll
    for (int j = 0; j < 8; j++) {
        int row = (tid + j * 128) >> 3;
        CP_ASYNC16(smb + (uint32_t)(row * PJ_STRIDE + ch_) * 2,
                   g_xh + (size_t)(m0 + row) * NDM + ch_);
        CP_ASYNC16(smb + (uint32_t)(PJ_TILE + row * PJ_STRIDE + ch_) * 2,
                   wt + (size_t)row * NDM + ch_);
    }
    CP_COMMIT;

    for (int s = 0; s < 16; s++) {
        if (s + 1 < 16) {
            const int k1 = (s + 1) * 64;
            const uint32_t sb = (uint32_t)(((s + 1) & 1) * PJ_STAGE);
            #pragma unroll
            for (int j = 0; j < 8; j++) {
                int row = (tid + j * 128) >> 3;
                CP_ASYNC16(smb + (sb + row * PJ_STRIDE + ch_) * 2,
                           g_xh + (size_t)(m0 + row) * NDM + k1 + ch_);
                CP_ASYNC16(smb + (sb + PJ_TILE + row * PJ_STRIDE + ch_) * 2,
                           wt + (size_t)row * NDM + k1 + ch_);
            }
            CP_COMMIT;
            CP_WAIT(1);
        } else {
            CP_WAIT(0);
        }
        __syncthreads();

        const uint32_t Ab = smb + (uint32_t)((s & 1) * PJ_STAGE) * 2 + aoff;
        const uint32_t Bb = smb + (uint32_t)((s & 1) * PJ_STAGE + PJ_TILE) * 2 + boff;

        #pragma unroll
        for (int ks2 = 0; ks2 < 2; ks2++) {
            uint32_t bfr[8][4];
            #pragma unroll
            for (int ni = 0; ni < 8; ni++)
                ldsm_x4(bfr[ni], Bb + (uint32_t)(ni * 8 * PJ_STRIDE * 2 + ks2 * 64));
            #pragma unroll
            for (int ks = 0; ks < 2; ks++) {
                uint32_t af[4][4];
                const uint32_t ka = (uint32_t)((ks2 * 2 + ks) * 32);
                #pragma unroll
                for (int mi = 0; mi < 4; mi++)
                    ldsm_x4(af[mi], Ab + (uint32_t)(mi * 16 * PJ_STRIDE * 2) + ka);
                #pragma unroll
                for (int mi = 0; mi < 4; mi++)
                    #pragma unroll
                    for (int ni = 0; ni < 8; ni++)
                        mma_f16(acc[mi][ni], af[mi], bfr[ni] + 2 * ks);
            }
        }
        __syncthreads();
    }

    const float QSC = 0.125f * 1.44269504088896340736f;
    const int b     = m0 >> 11;
    const int tbase = m0 & 2047;

    if (z < 2) {
        #pragma unroll
        for (int mi = 0; mi < 4; mi++) {
            const int t0 = tbase + wr * 64 + mi * 16 + qr;
            #pragma unroll
            for (int ni = 0; ni < 8; ni++) {
                const int ncta = wc * 64 + ni * 8 + 2 * qc;
                const int ng   = n0 + ncta;
                const int h    = ng >> 6;
                const int d    = ng & 63;
                const size_t bh = (size_t)(b * NH + h);
                if (z == 0) {
                    *(__half2*)&g_qh[(bh * NT + t0) * NDK + d] =
                        __floats2half2_rn(acc[mi][ni][0] * QSC, acc[mi][ni][1] * QSC);
                    *(__half2*)&g_qh[(bh * NT + t0 + 8) * NDK + d] =
                        __floats2half2_rn(acc[mi][ni][2] * QSC, acc[mi][ni][3] * QSC);
                } else {
                    *(__half2*)&g_kh[(bh * NT + t0) * NDK + d] =
                        __floats2half2_rn(acc[mi][ni][0], acc[mi][ni][1]);
                    *(__half2*)&g_kh[(bh * NT + t0 + 8) * NDK + d] =
                        __floats2half2_rn(acc[mi][ni][2], acc[mi][ni][3]);
                }
            }
        }
    } else {
        // V: stage transposed [d][t] then coalesced copy-out
        #pragma unroll
        for (int mi = 0; mi < 4; mi++) {
            const int tl = wr * 64 + mi * 16 + qr;
            #pragma unroll
            for (int ni = 0; ni < 8; ni++) {
                const int dl = wc * 64 + ni * 8 + 2 * qc;
                smh[(dl    ) * VST + tl    ] = __float2half_rn(acc[mi][ni][0]);
                smh[(dl + 1) * VST + tl    ] = __float2half_rn(acc[mi][ni][1]);
                smh[(dl    ) * VST + tl + 8] = __float2half_rn(acc[mi][ni][2]);
                smh[(dl + 1) * VST + tl + 8] = __float2half_rn(acc[mi][ni][3]);
            }
        }
        __syncthreads();
        const int cr = tid >> 4;          // 0..7
        const int cc = (tid & 15) * 8;
        #pragma unroll
        for (int j = 0; j < 16; j++) {
            const int r  = cr + j * 8;    // 0..127
            const int ng = n0 + r;
            const int h  = ng >> 6;
            const int d  = ng & 63;
            __half* dst = g_vt + ((size_t)(b * NH + h) * NDK + d) * NT + tbase + cc;
            *(float4*)dst = *(const float4*)&smh[r * VST + cc];
        }
    }
}

// ---------------------------------------------------------------------------
// Flash attention v5: q-tile 128, 4 warps (32 q-rows = 2 strips each),
// K/V fragments shared across both strips (halves smem traffic per mma).
// Triple-buffered 64-key tiles, ones-column row sums, f16x2 exp2.
// Smem halves: Q 128x72 | K 3x64x72 | V 3x64x72 = 36864 (73728 B).
// ---------------------------------------------------------------------------
#define AT_STRIDE 72
#define AT_TILEH  (64 * AT_STRIDE)
#define AT_KOFF   (128 * AT_STRIDE)
#define AT_VOFF   (AT_KOFF + 3 * AT_TILEH)
#define AT_SMEM   ((AT_VOFF + 3 * AT_TILEH) * 2)   // 73728 B

__global__ __launch_bounds__(128, 2) void attn_h(float* __restrict__ out)
{
    extern __shared__ __half smh[];
    const uint32_t smb = smem_u32(smh);

    const int qt = 15 - (int)blockIdx.x;
    const int bh = blockIdx.y;
    const int b  = bh >> 4;
    const int h  = bh & 15;
    const int q0 = qt * 128;

    const __half* qg = g_qh + (size_t)bh * NT * NDK;
    const __half* kg = g_kh + (size_t)bh * NT * NDK;
    const __half* vg = g_vt + (size_t)bh * NDK * NT;

    const int tid  = threadIdx.x;
    const int wid  = tid >> 5;
    const int lane = tid & 31;
    const int qr   = lane >> 2;
    const int qc   = lane & 3;

    const int ch_  = (tid & 7) * 8;

    const uint32_t lmoff = (uint32_t)(((lane & 7) * AT_STRIDE + (lane >> 3) * 8) * 2);

    // Q tile: 128x64 halves = 1024 chunks
    #pragma unroll
    for (int j = 0; j < 8; j++) {
        int row = (tid + j * 128) >> 3;
        CP_ASYNC16(smb + (uint32_t)(row * AT_STRIDE + ch_) * 2,
                   qg + (size_t)(q0 + row) * NDK + ch_);
    }
    CP_COMMIT;

    // K/V tile 0 (64x64 each = 512 chunks)
    #pragma unroll
    for (int j = 0; j < 4; j++) {
        int row = (tid + j * 128) >> 3;
        CP_ASYNC16(smb + (uint32_t)(AT_KOFF + row * AT_STRIDE + ch_) * 2,
                   kg + (size_t)row * NDK + ch_);
        CP_ASYNC16(smb + (uint32_t)(AT_VOFF + row * AT_STRIDE + ch_) * 2,
                   vg + (size_t)row * NT + ch_);
    }
    CP_COMMIT;

    CP_WAIT(1);
    __syncthreads();

    // Q fragments, both strips (rows wid*32 + s*16 + {qr, qr+8})
    uint32_t qf[2][4][4];
    #pragma unroll
    for (int s = 0; s < 2; s++) {
        const __half* Qw = smh + (wid * 32 + s * 16) * AT_STRIDE;
        #pragma unroll
        for (int ks = 0; ks < 4; ks++) {
            const __half* p = Qw + qr * AT_STRIDE + ks * 16 + 2 * qc;
            qf[s][ks][0] = *(const uint32_t*)(p);
            qf[s][ks][1] = *(const uint32_t*)(p + 8 * AT_STRIDE);
            qf[s][ks][2] = *(const uint32_t*)(p + 8);
            qf[s][ks][3] = *(const uint32_t*)(p + 8 * AT_STRIDE + 8);
        }
    }

    float o[2][8][4];
    #pragma unroll
    for (int s = 0; s < 2; s++)
        #pragma unroll
        for (int ni = 0; ni < 8; ni++)
            #pragma unroll
            for (int v = 0; v < 4; v++) o[s][ni][v] = 0.0f;
    float lsum[2][4] = {{0,0,0,0},{0,0,0,0}};
    float mA[2] = {-INFINITY, -INFINITY};   // rows qr
    float mB[2] = {-INFINITY, -INFINITY};   // rows qr+8

    const uint32_t bones[2] = {0x3C003C00u, 0x3C003C00u};
    const int ntiles = 2 * qt + 2;

    int cur = 0, nxt = 1;
    for (int kt = 0; kt < ntiles; kt++) {
        if (kt + 1 < ntiles) {
            const int s1 = (kt + 1) * 64;
            const uint32_t kb = AT_KOFF + (uint32_t)(nxt * AT_TILEH);
            const uint32_t vb = AT_VOFF + (uint32_t)(nxt * AT_TILEH);
            #pragma unroll
            for (int j = 0; j < 4; j++) {
                int row = (tid + j * 128) >> 3;
                CP_ASYNC16(smb + (kb + row * AT_STRIDE + ch_) * 2,
                           kg + (size_t)(s1 + row) * NDK + ch_);
                CP_ASYNC16(smb + (vb + row * AT_STRIDE + ch_) * 2,
                           vg + (size_t)row * NT + s1 + ch_);
            }
            CP_COMMIT;
            CP_WAIT(1);
        } else {
            CP_WAIT(0);
        }
        __syncthreads();

        const uint32_t Kb = smb + (AT_KOFF + cur * AT_TILEH) * 2 + lmoff;
        const uint32_t Vb = smb + (AT_VOFF + cur * AT_TILEH) * 2 + lmoff;
        const int s0 = kt * 64;

        // ---- S both strips; K fragments shared ----
        float sc[2][8][4];
        #pragma unroll
        for (int s = 0; s < 2; s++)
            #pragma unroll
            for (int ni = 0; ni < 8; ni++)
                #pragma unroll
                for (int v = 0; v < 4; v++) sc[s][ni][v] = 0.0f;

        #pragma unroll
        for (int ni = 0; ni < 8; ni++) {
            const uint32_t base = Kb + (uint32_t)(ni * 8 * AT_STRIDE * 2);
            uint32_t kf[4];
            ldsm_x4(kf, base);              // k 0..31
            mma_f16(sc[0][ni], qf[0][0], kf);
            mma_f16(sc[0][ni], qf[0][1], kf + 2);
            mma_f16(sc[1][ni], qf[1][0], kf);
            mma_f16(sc[1][ni], qf[1][1], kf + 2);
            ldsm_x4(kf, base + 64);         // k 32..63
            mma_f16(sc[0][ni], qf[0][2], kf);
            mma_f16(sc[0][ni], qf[0][3], kf + 2);
            mma_f16(sc[1][ni], qf[1][2], kf);
            mma_f16(sc[1][ni], qf[1][3], kf + 2);
        }

        // ---- causal mask (diagonal-overlap tiles) ----
        if (kt >= 2 * qt) {
            #pragma unroll
            for (int s = 0; s < 2; s++) {
                const int r0g = q0 + wid * 32 + s * 16 + qr;
                const int r1g = r0g + 8;
                #pragma unroll
                for (int ni = 0; ni < 8; ni++) {
                    const int c = s0 + ni * 8 + 2 * qc;
                    if (c     > r0g) sc[s][ni][0] = -INFINITY;
                    if (c + 1 > r0g) sc[s][ni][1] = -INFINITY;
                    if (c     > r1g) sc[s][ni][2] = -INFINITY;
                    if (c + 1 > r1g) sc[s][ni][3] = -INFINITY;
                }
            }
        }

        // ---- softmax per strip + pf ----
        uint32_t pf[2][4][4];
        #pragma unroll
        for (int s = 0; s < 2; s++) {
            float rmax0 = sc[s][0][0], rmax1 = sc[s][0][2];
            #pragma unroll
            for (int ni = 0; ni < 8; ni++) {
                rmax0 = fmaxf(rmax0, fmaxf(sc[s][ni][0], sc[s][ni][1]));
                rmax1 = fmaxf(rmax1, fmaxf(sc[s][ni][2], sc[s][ni][3]));
            }
            rmax0 = fmaxf(rmax0, __shfl_xor_sync(0xffffffffu, rmax0, 1));
            rmax0 = fmaxf(rmax0, __shfl_xor_sync(0xffffffffu, rmax0, 2));
            rmax1 = fmaxf(rmax1, __shfl_xor_sync(0xffffffffu, rmax1, 1));
            rmax1 = fmaxf(rmax1, __shfl_xor_sync(0xffffffffu, rmax1, 2));

            const float mn0 = fmaxf(mA[s], rmax0);
            const float mn1 = fmaxf(mB[s], rmax1);
            const float a0  = exp2f(mA[s] - mn0);
            const float a1  = exp2f(mB[s] - mn1);
            mA[s] = mn0;  mB[s] = mn1;

            #pragma unroll
            for (int ni = 0; ni < 8; ni++) {
                o[s][ni][0] *= a0; o[s][ni][1] *= a0;
                o[s][ni][2] *= a1; o[s][ni][3] *= a1;
            }
            lsum[s][0] *= a0;  lsum[s][2] *= a1;

            #pragma unroll
            for (int ks = 0; ks < 4; ks++) {
                pf[s][ks][0] = h2e(sc[s][2*ks    ][0] - mn0, sc[s][2*ks    ][1] - mn0);
                pf[s][ks][1] = h2e(sc[s][2*ks    ][2] - mn1, sc[s][2*ks    ][3] - mn1);
                pf[s][ks][2] = h2e(sc[s][2*ks + 1][0] - mn0, sc[s][2*ks + 1][1] - mn0);
                pf[s][ks][3] = h2e(sc[s][2*ks + 1][2] - mn1, sc[s][2*ks + 1][3] - mn1);
            }

            mma_f16(lsum[s], pf[s][0], bones);
            mma_f16(lsum[s], pf[s][1], bones);
            mma_f16(lsum[s], pf[s][2], bones);
            mma_f16(lsum[s], pf[s][3], bones);
        }

        // ---- O += P V; V fragments shared across strips ----
        #pragma unroll
        for (int ni = 0; ni < 8; ni++) {
            const uint32_t base = Vb + (uint32_t)(ni * 8 * AT_STRIDE * 2);
            uint32_t vf[4];
            ldsm_x4(vf, base);
            mma_f16(o[0][ni], pf[0][0], vf);
            mma_f16(o[0][ni], pf[0][1], vf + 2);
            mma_f16(o[1][ni], pf[1][0], vf);
            mma_f16(o[1][ni], pf[1][1], vf + 2);
            ldsm_x4(vf, base + 64);
            mma_f16(o[0][ni], pf[0][2], vf);
            mma_f16(o[0][ni], pf[0][3], vf + 2);
            mma_f16(o[1][ni], pf[1][2], vf);
            mma_f16(o[1][ni], pf[1][3], vf + 2);
        }

        cur = nxt;
        nxt = (nxt == 2) ? 0 : nxt + 1;
    }

    // ---- finalize + write out ----
    #pragma unroll
    for (int s = 0; s < 2; s++) {
        const float inv0 = 1.0f / lsum[s][0];
        const float inv1 = 1.0f / lsum[s][2];
        const int t0 = q0 + wid * 32 + s * 16 + qr;
        size_t base0 = ((size_t)b * NT + t0) * (NH * NDK) + h * NDK;
        size_t base1 = base0 + 8 * (size_t)(NH * NDK);
        #pragma unroll
        for (int ni = 0; ni < 8; ni++) {
            const int n = ni * 8 + 2 * qc;
            *(float2*)&out[base0 + n] =
                make_float2(o[s][ni][0] * inv0, o[s][ni][1] * inv0);
            *(float2*)&out[base1 + n] =
                make_float2(o[s][ni][2] * inv1, o[s][ni][3] * inv1);
        }
    }
}

// ---------------------------------------------------------------------------
extern "C" void kernel_launch(void* const* d_in, const int* in_sizes, int n_in,
                              void* d_out, int out_size)
{
    (void)in_sizes; (void)n_in; (void)out_size;
    const float* x  = (const float*)d_in[0];
    const float* Wq = (const float*)d_in[1];
    const float* Wk = (const float*)d_in[2];
    const float* Wv = (const float*)d_in[3];
    float* out = (float*)d_out;

    cudaFuncSetAttribute(proj_h,
                         cudaFuncAttributeMaxDynamicSharedMemorySize, PJ_SMEM);
    cudaFuncSetAttribute(attn_h,
                         cudaFuncAttributeMaxDynamicSharedMemorySize, AT_SMEM);

    convert_x<<<NB * NT * NDM / 1024, 256>>>(x);
    convert_w<<<dim3(NDM / 32, NDK / 32, 48), dim3(32, 8)>>>(Wq, Wk, Wv);

    proj_h<<<dim3(NB * NT / 128, 24), 128, PJ_SMEM>>>();

    attn_h<<<dim3(NT / 128, NB * NH), 128, AT_SMEM>>>(out);
}